// round 3
// baseline (speedup 1.0000x reference)
#include <cuda_runtime.h>
#include <cuda_bf16.h>

// Problem constants
#define LL   2048
#define SS   2048
#define NB   4
#define EE   1024
#define HH   16
#define DH   64

// Scratch (device globals: allocation-free per harness rules)
__device__ float g_Qh[(size_t)NB * HH * LL * DH];   // [n,h,l,d]  32 MB
__device__ float g_Kh[(size_t)NB * HH * SS * DH];   // [n,h,s,d]  32 MB
__device__ float g_Vt[(size_t)NB * HH * DH * SS];   // [n,h,d,s]  32 MB (transposed V)
__device__ float g_scores[(size_t)NB * HH * LL * SS]; // [n,h,l,s] 1 GB (scores -> probs in place)
__device__ float g_ctx[(size_t)LL * NB * EE];       // [l,n,e]    32 MB

// ---------------------------------------------------------------------------
// Generic tiled fp32 GEMM: C = alpha * A[M,K] @ B[N,K]^T (+ bias), with
// MODE-specific sources and output scatter.
// MODE 0: Q proj   A=query[L*NB,E] B=Wq  -> g_Qh scatter
// MODE 1: K proj   A=key          B=Wk  -> g_Kh scatter
// MODE 2: V proj   A=value        B=Wv  -> g_Vt scatter (transposed)
// MODE 3: scores   per z=(n*H+h): Qh_z[L,D] @ Kh_z[S,D]^T * 1/8 -> g_scores
// MODE 4: P @ V    per z: probs_z[L,S] @ Vt_z[D,S]^T -> g_ctx scatter
// MODE 5: out proj A=g_ctx[L*NB,E] B=Wo -> d_out[0:L*NB*E]
// ---------------------------------------------------------------------------
template<int MODE>
__global__ void __launch_bounds__(256)
gemm_k(const float* __restrict__ Ain, const float* __restrict__ Bin,
       const float* __restrict__ bias, float* __restrict__ Cout)
{
    constexpr int BM = 128;
    constexpr int BN = (MODE == 4) ? 64 : 128;
    constexpr int BK = 8;
    constexpr int TM = 8;
    constexpr int TN = (MODE == 4) ? 4 : 8;
    constexpr int KK = (MODE == 3) ? DH : ((MODE == 4) ? SS : EE);
    constexpr bool HASB = (MODE <= 2 || MODE == 5);

    const int z = blockIdx.z;
    const float* A;
    const float* B;
    if constexpr (MODE <= 2)      { A = Ain; B = Bin; }
    else if constexpr (MODE == 3) { A = g_Qh + (size_t)z * LL * DH;
                                    B = g_Kh + (size_t)z * SS * DH; }
    else if constexpr (MODE == 4) { A = g_scores + (size_t)z * LL * SS;
                                    B = g_Vt + (size_t)z * DH * SS; }
    else                          { A = g_ctx; B = Bin; }

    const int bm0 = blockIdx.y * BM;
    const int bn0 = blockIdx.x * BN;

    __shared__ float As[BK][BM];
    __shared__ float Bs[BK][BN];

    const int t  = threadIdx.x;          // 0..255
    const int tx = t & 15;
    const int ty = t >> 4;
    const int m0 = ty * TM;              // 0..120
    const int n0 = tx * TN;              // 0..(BN-TN)

    // loader mapping: each thread loads one float4 per tile per matrix
    const int lr = t >> 1;               // tile row 0..127
    const int lc = (t & 1) * 4;          // k-chunk 0 or 4

    float acc[TM][TN];
    #pragma unroll
    for (int i = 0; i < TM; i++)
        #pragma unroll
        for (int j = 0; j < TN; j++) acc[i][j] = 0.0f;

    const float* Aptr = A + (size_t)(bm0 + lr) * KK + lc;
    const float* Bptr = B + (size_t)(bn0 + lr) * KK + lc;   // valid only when lr < BN

    for (int k0 = 0; k0 < KK; k0 += BK) {
        float4 av = *(const float4*)(Aptr + k0);
        As[lc + 0][lr] = av.x; As[lc + 1][lr] = av.y;
        As[lc + 2][lr] = av.z; As[lc + 3][lr] = av.w;
        if (BN == 128 || t < 128) {
            float4 bv = *(const float4*)(Bptr + k0);
            Bs[lc + 0][lr] = bv.x; Bs[lc + 1][lr] = bv.y;
            Bs[lc + 2][lr] = bv.z; Bs[lc + 3][lr] = bv.w;
        }
        __syncthreads();

        #pragma unroll
        for (int k = 0; k < BK; k++) {
            float a[TM], b[TN];
            #pragma unroll
            for (int i = 0; i < TM; i += 4)
                *(float4*)&a[i] = *(const float4*)&As[k][m0 + i];
            #pragma unroll
            for (int j = 0; j < TN; j += 4)
                *(float4*)&b[j] = *(const float4*)&Bs[k][n0 + j];
            #pragma unroll
            for (int i = 0; i < TM; i++)
                #pragma unroll
                for (int j = 0; j < TN; j++)
                    acc[i][j] = fmaf(a[i], b[j], acc[i][j]);
        }
        __syncthreads();
    }

    // epilogue: per-mode scatter
    #pragma unroll
    for (int i = 0; i < TM; i++) {
        const int gi = bm0 + m0 + i;
        #pragma unroll
        for (int j = 0; j < TN; j++) {
            const int gj = bn0 + n0 + j;
            float v = acc[i][j];
            if constexpr (MODE == 3) v *= 0.125f;     // 1/sqrt(64)
            if constexpr (HASB) v += bias[gj];

            if constexpr (MODE == 0) {
                const int l = gi >> 2, n = gi & 3, h = gj >> 6, d = gj & 63;
                g_Qh[(((size_t)(n * HH + h) * LL) + l) * DH + d] = v;
            } else if constexpr (MODE == 1) {
                const int s = gi >> 2, n = gi & 3, h = gj >> 6, d = gj & 63;
                g_Kh[(((size_t)(n * HH + h) * SS) + s) * DH + d] = v;
            } else if constexpr (MODE == 2) {
                const int s = gi >> 2, n = gi & 3, h = gj >> 6, d = gj & 63;
                g_Vt[(((size_t)(n * HH + h) * DH) + d) * SS + s] = v;
            } else if constexpr (MODE == 3) {
                g_scores[(size_t)z * LL * SS + (size_t)gi * SS + gj] = v;
            } else if constexpr (MODE == 4) {
                const int n = z >> 4, h = z & 15;
                g_ctx[(size_t)gi * (NB * EE) + n * EE + h * DH + gj] = v;
            } else {
                Cout[(size_t)gi * EE + gj] = v;
            }
        }
    }
}

// ---------------------------------------------------------------------------
// Fast exp on the FMA pipe (avoids MUFU.EX2 bottleneck: 268M exps would cost
// ~1.9 ms at 74 MUFU/cyc chip-wide; polynomial runs in ~60 us).
// exp(x) = 2^(x*log2e); split integer/fraction, 5-term Taylor of e^(f*ln2),
// f in [-0.5,0.5], abs poly error ~2.4e-6 -> fine vs 1e-3 tolerance.
// ---------------------------------------------------------------------------
__device__ __forceinline__ float fexp(float x)
{
    float y = x * 1.4426950408889634f;
    y = fmaxf(y, -120.0f);                 // underflow clamp (result ~0)
    float r = rintf(y);
    float f = y - r;                       // [-0.5, 0.5]
    float p = 1.3333558146e-3f;
    p = fmaf(p, f, 9.6181291076e-3f);
    p = fmaf(p, f, 5.5504108665e-2f);
    p = fmaf(p, f, 2.4022650696e-1f);
    p = fmaf(p, f, 6.9314718056e-1f);
    p = fmaf(p, f, 1.0f);
    int i = (int)r;
    float sc = __int_as_float((i + 127) << 23);
    return p * sc;
}

// ---------------------------------------------------------------------------
// Fused per-(n,l) softmax over all 16 heads + running head-average.
// Block = (n,l); 256 threads, 8 elems/thread over S=2048.
// Probs written back to g_scores in place; mean written to wavg[n,l,s].
// ---------------------------------------------------------------------------
__global__ void __launch_bounds__(256)
softmax_mean_k(float* __restrict__ wavg)
{
    const int b = blockIdx.x;        // n*L + l
    const int n = b >> 11;
    const int l = b & 2047;
    const int t = threadIdx.x;

    __shared__ float sh[8];
    float mean[8];
    #pragma unroll
    for (int i = 0; i < 8; i++) mean[i] = 0.0f;

    for (int h = 0; h < HH; h++) {
        float* row = g_scores + (((size_t)(n * HH + h) * LL) + l) * SS;
        float x[8];
        #pragma unroll
        for (int i = 0; i < 8; i++) x[i] = row[t + 256 * i];

        // block max
        float m = x[0];
        #pragma unroll
        for (int i = 1; i < 8; i++) m = fmaxf(m, x[i]);
        #pragma unroll
        for (int o = 16; o > 0; o >>= 1) m = fmaxf(m, __shfl_xor_sync(0xffffffffu, m, o));
        if ((t & 31) == 0) sh[t >> 5] = m;
        __syncthreads();
        m = sh[t & 7];
        #pragma unroll
        for (int o = 4; o > 0; o >>= 1) m = fmaxf(m, __shfl_xor_sync(0xffffffffu, m, o));

        // exp + block sum
        float s = 0.0f;
        #pragma unroll
        for (int i = 0; i < 8; i++) { x[i] = fexp(x[i] - m); s += x[i]; }
        #pragma unroll
        for (int o = 16; o > 0; o >>= 1) s += __shfl_xor_sync(0xffffffffu, s, o);
        __syncthreads();                 // sh reuse safety
        if ((t & 31) == 0) sh[t >> 5] = s;
        __syncthreads();
        s = sh[t & 7];
        #pragma unroll
        for (int o = 4; o > 0; o >>= 1) s += __shfl_xor_sync(0xffffffffu, s, o);

        const float inv = 1.0f / s;
        #pragma unroll
        for (int i = 0; i < 8; i++) {
            const float p = x[i] * inv;
            row[t + 256 * i] = p;
            mean[i] += p;
        }
        __syncthreads();                 // before next head overwrites sh
    }

    float* w = wavg + (size_t)b * SS;
    const float ih = 1.0f / (float)HH;
    #pragma unroll
    for (int i = 0; i < 8; i++) w[t + 256 * i] = mean[i] * ih;
}

// ---------------------------------------------------------------------------
// Launch: Q/K/V proj -> scores -> softmax+mean -> P@V -> out proj
// Inputs (metadata order): query key value Wq bq Wk bk Wv bv Wo bo
// Output: [ attn_output (L*N*E) | attn_weights_mean (N*L*S) ]
// ---------------------------------------------------------------------------
extern "C" void kernel_launch(void* const* d_in, const int* in_sizes, int n_in,
                              void* d_out, int out_size)
{
    const float* query = (const float*)d_in[0];
    const float* key   = (const float*)d_in[1];
    const float* value = (const float*)d_in[2];
    const float* Wq    = (const float*)d_in[3];
    const float* bq    = (const float*)d_in[4];
    const float* Wk    = (const float*)d_in[5];
    const float* bk    = (const float*)d_in[6];
    const float* Wv    = (const float*)d_in[7];
    const float* bv    = (const float*)d_in[8];
    const float* Wo    = (const float*)d_in[9];
    const float* bo    = (const float*)d_in[10];
    float* out = (float*)d_out;
    float* wavg = out + (size_t)LL * NB * EE;   // 8,388,608 offset

    dim3 thr(256);
    // projections: M = L*NB = 8192, N = E = 1024, K = E
    gemm_k<0><<<dim3(EE / 128, (LL * NB) / 128, 1), thr>>>(query, Wq, bq, nullptr);
    gemm_k<1><<<dim3(EE / 128, (SS * NB) / 128, 1), thr>>>(key,   Wk, bk, nullptr);
    gemm_k<2><<<dim3(EE / 128, (SS * NB) / 128, 1), thr>>>(value, Wv, bv, nullptr);
    // scores: per (n,h) 2048x2048x64
    gemm_k<3><<<dim3(SS / 128, LL / 128, NB * HH), thr>>>(nullptr, nullptr, nullptr, nullptr);
    // softmax + head mean
    softmax_mean_k<<<NB * LL, thr>>>(wavg);
    // P @ V: per (n,h) 2048x64x2048
    gemm_k<4><<<dim3(1, LL / 128, NB * HH), thr>>>(nullptr, nullptr, nullptr, nullptr);
    // output projection
    gemm_k<5><<<dim3(EE / 128, (LL * NB) / 128, 1), thr>>>(nullptr, Wo, bo, out);
}

// round 4
// speedup vs baseline: 1.0003x; 1.0003x over previous
#include <cuda_runtime.h>
#include <cuda_bf16.h>

// Problem constants
#define LL   2048
#define SS   2048
#define NB   4
#define EE   1024
#define HH   16
#define DH   64

// Scratch (device globals: allocation-free per harness rules)
__device__ float g_Qh[(size_t)NB * HH * LL * DH];   // [n,h,l,d]  32 MB
__device__ float g_Kh[(size_t)NB * HH * SS * DH];   // [n,h,s,d]  32 MB
__device__ float g_Vt[(size_t)NB * HH * DH * SS];   // [n,h,d,s]  32 MB (transposed V)
__device__ float g_scores[(size_t)NB * HH * LL * SS]; // [n,h,l,s] 1 GB (scores -> probs in place)
__device__ float g_ctx[(size_t)LL * NB * EE];       // [l,n,e]    32 MB

// ---------------------------------------------------------------------------
// Generic tiled fp32 GEMM: C = alpha * A[M,K] @ B[N,K]^T (+ bias), with
// MODE-specific sources and output scatter.
// MODE 0: Q proj   A=query[L*NB,E] B=Wq  -> g_Qh scatter
// MODE 1: K proj   A=key          B=Wk  -> g_Kh scatter
// MODE 2: V proj   A=value        B=Wv  -> g_Vt scatter (transposed)
// MODE 3: scores   per z=(n*H+h): Qh_z[L,D] @ Kh_z[S,D]^T * 1/8 -> g_scores
// MODE 4: P @ V    per z: probs_z[L,S] @ Vt_z[D,S]^T -> g_ctx scatter
// MODE 5: out proj A=g_ctx[L*NB,E] B=Wo -> d_out[0:L*NB*E]
// ---------------------------------------------------------------------------
template<int MODE>
__global__ void __launch_bounds__(256)
gemm_k(const float* __restrict__ Ain, const float* __restrict__ Bin,
       const float* __restrict__ bias, float* __restrict__ Cout)
{
    constexpr int BM = 128;
    constexpr int BN = (MODE == 4) ? 64 : 128;
    constexpr int BK = 8;
    constexpr int TM = 8;
    constexpr int TN = (MODE == 4) ? 4 : 8;
    constexpr int KK = (MODE == 3) ? DH : ((MODE == 4) ? SS : EE);
    constexpr bool HASB = (MODE <= 2 || MODE == 5);

    const int z = blockIdx.z;
    const float* A;
    const float* B;
    if constexpr (MODE <= 2)      { A = Ain; B = Bin; }
    else if constexpr (MODE == 3) { A = g_Qh + (size_t)z * LL * DH;
                                    B = g_Kh + (size_t)z * SS * DH; }
    else if constexpr (MODE == 4) { A = g_scores + (size_t)z * LL * SS;
                                    B = g_Vt + (size_t)z * DH * SS; }
    else                          { A = g_ctx; B = Bin; }

    const int bm0 = blockIdx.y * BM;
    const int bn0 = blockIdx.x * BN;

    __shared__ float As[BK][BM];
    __shared__ float Bs[BK][BN];

    const int t  = threadIdx.x;          // 0..255
    const int tx = t & 15;
    const int ty = t >> 4;
    const int m0 = ty * TM;              // 0..120
    const int n0 = tx * TN;              // 0..(BN-TN)

    // loader mapping: each thread loads one float4 per tile per matrix
    const int lr = t >> 1;               // tile row 0..127
    const int lc = (t & 1) * 4;          // k-chunk 0 or 4

    float acc[TM][TN];
    #pragma unroll
    for (int i = 0; i < TM; i++)
        #pragma unroll
        for (int j = 0; j < TN; j++) acc[i][j] = 0.0f;

    const float* Aptr = A + (size_t)(bm0 + lr) * KK + lc;
    const float* Bptr = B + (size_t)(bn0 + lr) * KK + lc;   // valid only when lr < BN

    for (int k0 = 0; k0 < KK; k0 += BK) {
        float4 av = *(const float4*)(Aptr + k0);
        As[lc + 0][lr] = av.x; As[lc + 1][lr] = av.y;
        As[lc + 2][lr] = av.z; As[lc + 3][lr] = av.w;
        if (BN == 128 || t < 128) {
            float4 bv = *(const float4*)(Bptr + k0);
            Bs[lc + 0][lr] = bv.x; Bs[lc + 1][lr] = bv.y;
            Bs[lc + 2][lr] = bv.z; Bs[lc + 3][lr] = bv.w;
        }
        __syncthreads();

        #pragma unroll
        for (int k = 0; k < BK; k++) {
            float a[TM], b[TN];
            #pragma unroll
            for (int i = 0; i < TM; i += 4)
                *(float4*)&a[i] = *(const float4*)&As[k][m0 + i];
            #pragma unroll
            for (int j = 0; j < TN; j += 4)
                *(float4*)&b[j] = *(const float4*)&Bs[k][n0 + j];
            #pragma unroll
            for (int i = 0; i < TM; i++)
                #pragma unroll
                for (int j = 0; j < TN; j++)
                    acc[i][j] = fmaf(a[i], b[j], acc[i][j]);
        }
        __syncthreads();
    }

    // epilogue: per-mode scatter
    #pragma unroll
    for (int i = 0; i < TM; i++) {
        const int gi = bm0 + m0 + i;
        #pragma unroll
        for (int j = 0; j < TN; j++) {
            const int gj = bn0 + n0 + j;
            float v = acc[i][j];
            if constexpr (MODE == 3) v *= 0.125f;     // 1/sqrt(64)
            if constexpr (HASB) v += bias[gj];

            if constexpr (MODE == 0) {
                const int l = gi >> 2, n = gi & 3, h = gj >> 6, d = gj & 63;
                g_Qh[(((size_t)(n * HH + h) * LL) + l) * DH + d] = v;
            } else if constexpr (MODE == 1) {
                const int s = gi >> 2, n = gi & 3, h = gj >> 6, d = gj & 63;
                g_Kh[(((size_t)(n * HH + h) * SS) + s) * DH + d] = v;
            } else if constexpr (MODE == 2) {
                const int s = gi >> 2, n = gi & 3, h = gj >> 6, d = gj & 63;
                g_Vt[(((size_t)(n * HH + h) * DH) + d) * SS + s] = v;
            } else if constexpr (MODE == 3) {
                g_scores[(size_t)z * LL * SS + (size_t)gi * SS + gj] = v;
            } else if constexpr (MODE == 4) {
                const int n = z >> 4, h = z & 15;
                g_ctx[(size_t)gi * (NB * EE) + n * EE + h * DH + gj] = v;
            } else {
                Cout[(size_t)gi * EE + gj] = v;
            }
        }
    }
}

// ---------------------------------------------------------------------------
// Fast exp on the FMA pipe (avoids MUFU.EX2 bottleneck: 268M exps would cost
// ~1.9 ms at 74 MUFU/cyc chip-wide; polynomial runs in ~60 us).
// exp(x) = 2^(x*log2e); split integer/fraction, 5-term Taylor of e^(f*ln2),
// f in [-0.5,0.5], abs poly error ~2.4e-6 -> fine vs 1e-3 tolerance.
// ---------------------------------------------------------------------------
__device__ __forceinline__ float fexp(float x)
{
    float y = x * 1.4426950408889634f;
    y = fmaxf(y, -120.0f);                 // underflow clamp (result ~0)
    float r = rintf(y);
    float f = y - r;                       // [-0.5, 0.5]
    float p = 1.3333558146e-3f;
    p = fmaf(p, f, 9.6181291076e-3f);
    p = fmaf(p, f, 5.5504108665e-2f);
    p = fmaf(p, f, 2.4022650696e-1f);
    p = fmaf(p, f, 6.9314718056e-1f);
    p = fmaf(p, f, 1.0f);
    int i = (int)r;
    float sc = __int_as_float((i + 127) << 23);
    return p * sc;
}

// ---------------------------------------------------------------------------
// Fused per-(n,l) softmax over all 16 heads + running head-average.
// Block = (n,l); 256 threads, 8 elems/thread over S=2048.
// Probs written back to g_scores in place; mean written to wavg[n,l,s].
// ---------------------------------------------------------------------------
__global__ void __launch_bounds__(256)
softmax_mean_k(float* __restrict__ wavg)
{
    const int b = blockIdx.x;        // n*L + l
    const int n = b >> 11;
    const int l = b & 2047;
    const int t = threadIdx.x;

    __shared__ float sh[8];
    float mean[8];
    #pragma unroll
    for (int i = 0; i < 8; i++) mean[i] = 0.0f;

    for (int h = 0; h < HH; h++) {
        float* row = g_scores + (((size_t)(n * HH + h) * LL) + l) * SS;
        float x[8];
        #pragma unroll
        for (int i = 0; i < 8; i++) x[i] = row[t + 256 * i];

        // block max
        float m = x[0];
        #pragma unroll
        for (int i = 1; i < 8; i++) m = fmaxf(m, x[i]);
        #pragma unroll
        for (int o = 16; o > 0; o >>= 1) m = fmaxf(m, __shfl_xor_sync(0xffffffffu, m, o));
        if ((t & 31) == 0) sh[t >> 5] = m;
        __syncthreads();
        m = sh[t & 7];
        #pragma unroll
        for (int o = 4; o > 0; o >>= 1) m = fmaxf(m, __shfl_xor_sync(0xffffffffu, m, o));

        // exp + block sum
        float s = 0.0f;
        #pragma unroll
        for (int i = 0; i < 8; i++) { x[i] = fexp(x[i] - m); s += x[i]; }
        #pragma unroll
        for (int o = 16; o > 0; o >>= 1) s += __shfl_xor_sync(0xffffffffu, s, o);
        __syncthreads();                 // sh reuse safety
        if ((t & 31) == 0) sh[t >> 5] = s;
        __syncthreads();
        s = sh[t & 7];
        #pragma unroll
        for (int o = 4; o > 0; o >>= 1) s += __shfl_xor_sync(0xffffffffu, s, o);

        const float inv = 1.0f / s;
        #pragma unroll
        for (int i = 0; i < 8; i++) {
            const float p = x[i] * inv;
            row[t + 256 * i] = p;
            mean[i] += p;
        }
        __syncthreads();                 // before next head overwrites sh
    }

    float* w = wavg + (size_t)b * SS;
    const float ih = 1.0f / (float)HH;
    #pragma unroll
    for (int i = 0; i < 8; i++) w[t + 256 * i] = mean[i] * ih;
}

// ---------------------------------------------------------------------------
// Launch: Q/K/V proj -> scores -> softmax+mean -> P@V -> out proj
// Inputs (metadata order): query key value Wq bq Wk bk Wv bv Wo bo
// Output: [ attn_output (L*N*E) | attn_weights_mean (N*L*S) ]
// ---------------------------------------------------------------------------
extern "C" void kernel_launch(void* const* d_in, const int* in_sizes, int n_in,
                              void* d_out, int out_size)
{
    const float* query = (const float*)d_in[0];
    const float* key   = (const float*)d_in[1];
    const float* value = (const float*)d_in[2];
    const float* Wq    = (const float*)d_in[3];
    const float* bq    = (const float*)d_in[4];
    const float* Wk    = (const float*)d_in[5];
    const float* bk    = (const float*)d_in[6];
    const float* Wv    = (const float*)d_in[7];
    const float* bv    = (const float*)d_in[8];
    const float* Wo    = (const float*)d_in[9];
    const float* bo    = (const float*)d_in[10];
    float* out = (float*)d_out;
    float* wavg = out + (size_t)LL * NB * EE;   // 8,388,608 offset

    dim3 thr(256);
    // projections: M = L*NB = 8192, N = E = 1024, K = E
    gemm_k<0><<<dim3(EE / 128, (LL * NB) / 128, 1), thr>>>(query, Wq, bq, nullptr);
    gemm_k<1><<<dim3(EE / 128, (SS * NB) / 128, 1), thr>>>(key,   Wk, bk, nullptr);
    gemm_k<2><<<dim3(EE / 128, (SS * NB) / 128, 1), thr>>>(value, Wv, bv, nullptr);
    // scores: per (n,h) 2048x2048x64
    gemm_k<3><<<dim3(SS / 128, LL / 128, NB * HH), thr>>>(nullptr, nullptr, nullptr, nullptr);
    // softmax + head mean
    softmax_mean_k<<<NB * LL, thr>>>(wavg);
    // P @ V: per (n,h) 2048x64x2048
    gemm_k<4><<<dim3(1, LL / 128, NB * HH), thr>>>(nullptr, nullptr, nullptr, nullptr);
    // output projection
    gemm_k<5><<<dim3(EE / 128, (LL * NB) / 128, 1), thr>>>(nullptr, Wo, bo, out);
}

// round 6
// speedup vs baseline: 2.4463x; 2.4455x over previous
#include <cuda_runtime.h>
#include <cuda_bf16.h>
#include <cstdint>

#define LLEN 2048
#define SLEN 2048
#define NBAT 4
#define EDIM 1024
#define NHEAD 16
#define DHEAD 64

// ---------------- device scratch (allocation-free rule) ----------------
__device__ float g_Qh[(size_t)NBAT*NHEAD*LLEN*DHEAD];    // [n,h,l,d]
__device__ float g_Kh[(size_t)NBAT*NHEAD*SLEN*DHEAD];    // [n,h,s,d]
__device__ float g_Vt[(size_t)NBAT*NHEAD*DHEAD*SLEN];    // [n,h,d,s]
__device__ float g_scores[(size_t)NBAT*NHEAD*LLEN*SLEN]; // [n,h,l,s]
__device__ float g_ctx[(size_t)LLEN*NBAT*EDIM];          // [l,n,e]

// ---------------- helpers ----------------
__device__ __forceinline__ uint32_t smem_u32(const void* p) {
    uint32_t a;
    asm("{ .reg .u64 t; cvta.to.shared.u64 t, %1; cvt.u32.u64 %0, t; }" : "=r"(a) : "l"(p));
    return a;
}
// bf16x2 with low half = cvt(a), high half = cvt(b)
__device__ __forceinline__ uint32_t bfpack(float a, float b) {
    uint32_t r;
    asm("cvt.rn.bf16x2.f32 %0, %1, %2;" : "=r"(r) : "f"(b), "f"(a));
    return r;
}
__device__ __forceinline__ void ldsm4(uint32_t& r0, uint32_t& r1, uint32_t& r2, uint32_t& r3,
                                      uint32_t addr) {
    asm volatile("ldmatrix.sync.aligned.m8n8.x4.shared.b16 {%0,%1,%2,%3}, [%4];"
                 : "=r"(r0), "=r"(r1), "=r"(r2), "=r"(r3) : "r"(addr));
}
__device__ __forceinline__ void mma16816(float* c, const uint32_t* a, const uint32_t* b) {
    asm volatile("mma.sync.aligned.m16n8k16.row.col.f32.bf16.bf16.f32 "
                 "{%0,%1,%2,%3}, {%4,%5,%6,%7}, {%8,%9}, {%0,%1,%2,%3};"
                 : "+f"(c[0]), "+f"(c[1]), "+f"(c[2]), "+f"(c[3])
                 : "r"(a[0]), "r"(a[1]), "r"(a[2]), "r"(a[3]), "r"(b[0]), "r"(b[1]));
}

// Load ROWS x 32-float K-major chunk -> bf16 hi/lo tiles in smem (swizzled).
// smem layout per tile: row r, 16B chunk kc: off = r*64 + ((kc ^ ((r>>1)&3))<<4)
template<int ROWS, int KP>
__device__ __forceinline__ void load_chunk(char* smp, uint32_t hiOff, uint32_t loOff,
                                           const float* __restrict__ src, int t)
{
    #pragma unroll
    for (int i = 0; i < ROWS / 64; i++) {
        const int idx = t + 256 * i;
        const int r = idx >> 2, kc = idx & 3;
        const float* g = src + (size_t)r * KP + kc * 8;
        const float4 v0 = *(const float4*)g;
        const float4 v1 = *(const float4*)(g + 4);
        float f[8] = { v0.x, v0.y, v0.z, v0.w, v1.x, v1.y, v1.z, v1.w };
        float h[8], l[8];
        #pragma unroll
        for (int j = 0; j < 8; j++) {
            h[j] = __bfloat162float(__float2bfloat16(f[j]));
            l[j] = f[j] - h[j];
        }
        uint4 h4, l4;
        h4.x = bfpack(h[0], h[1]); h4.y = bfpack(h[2], h[3]);
        h4.z = bfpack(h[4], h[5]); h4.w = bfpack(h[6], h[7]);
        l4.x = bfpack(l[0], l[1]); l4.y = bfpack(l[2], l[3]);
        l4.z = bfpack(l[4], l[5]); l4.w = bfpack(l[6], l[7]);
        const uint32_t off = r * 64 + ((uint32_t)(kc ^ ((r >> 1) & 3)) << 4);
        *(uint4*)(smp + hiOff + off) = h4;
        *(uint4*)(smp + loOff + off) = l4;
    }
}

// ---------------------------------------------------------------------------
// mma.sync bf16-split GEMM: C = A[M,K] @ B[N,K]^T  (fp32-grade accuracy)
// MODE 0/1/2: QKV proj (+bias) -> g_Qh/g_Kh/g_Vt scatter
// MODE 3: scores per (n,h), K=64, *0.125 -> g_scores
// MODE 4: probs @ Vt^T per (n,h), K=2048 -> g_ctx
// MODE 5: out proj (+bias) -> Cout
// ---------------------------------------------------------------------------
template<int MODE>
__global__ void __launch_bounds__(256, 2)
mma_gemm(const float* __restrict__ Ain, const float* __restrict__ Bin,
         const float* __restrict__ bias, float* __restrict__ Cout)
{
    constexpr int BN = (MODE == 4) ? 64 : 128;
    constexpr int KK = (MODE == 3) ? 64 : ((MODE == 4) ? 2048 : 1024);
    constexpr int NC = KK / 32;
    constexpr int WN = BN / 4;           // warp n extent (32 or 16)
    constexpr int NT = WN / 8;           // n tiles per warp (4 or 2)
    constexpr int NP = NT / 2;           // ldmatrix x4 pairs
    constexpr uint32_t AHI = 0, ALO = 8192, BHI = 16384;
    constexpr uint32_t BLO = 16384 + (uint32_t)BN * 64;

    extern __shared__ char smp[];
    const int t = threadIdx.x, lane = t & 31, wid = t >> 5;
    const int wm = (wid >> 2) * 64;
    const int wn = (wid & 3) * WN;
    const int bm0 = blockIdx.y * 128, bn0 = blockIdx.x * BN, z = blockIdx.z;

    const float* Asrc; const float* Bsrc;
    if constexpr (MODE <= 2)      { Asrc = Ain + (size_t)bm0 * KK;
                                    Bsrc = Bin + (size_t)bn0 * KK; }
    else if constexpr (MODE == 3) { Asrc = g_Qh + (size_t)z * LLEN * DHEAD + (size_t)bm0 * KK;
                                    Bsrc = g_Kh + (size_t)z * SLEN * DHEAD + (size_t)bn0 * KK; }
    else if constexpr (MODE == 4) { Asrc = g_scores + (size_t)z * LLEN * SLEN + (size_t)bm0 * KK;
                                    Bsrc = g_Vt + (size_t)z * DHEAD * SLEN; }
    else                          { Asrc = g_ctx + (size_t)bm0 * KK;
                                    Bsrc = Bin + (size_t)bn0 * KK; }

    float acc[4][NT][4];
    #pragma unroll
    for (int m = 0; m < 4; m++)
        #pragma unroll
        for (int n = 0; n < NT; n++)
            #pragma unroll
            for (int v = 0; v < 4; v++) acc[m][n][v] = 0.0f;

    // lane-fixed address components
    const int arow  = wm + ((lane >> 3) & 1) * 8 + (lane & 7);  // + mt*16
    const int acsel = lane >> 4;                                // A k-chunk sub
    const int brow  = wn + (lane >> 4) * 8 + (lane & 7);        // + p*16
    const int bcsel = (lane >> 3) & 1;                          // B k-chunk sub
    const uint32_t smb = smem_u32(smp);

    for (int c = 0; c < NC; c++) {
        load_chunk<128, KK>(smp, AHI, ALO, Asrc + c * 32, t);
        load_chunk<BN,  KK>(smp, BHI, BLO, Bsrc + c * 32, t);
        __syncthreads();
        #pragma unroll
        for (int kk = 0; kk < 2; kk++) {
            uint32_t Bh[NT][2], Bl[NT][2];
            #pragma unroll
            for (int p = 0; p < NP; p++) {
                const int r = brow + p * 16;
                const uint32_t ba = smb + BHI + r * 64 +
                    ((uint32_t)((kk * 2 + bcsel) ^ ((r >> 1) & 3)) << 4);
                ldsm4(Bh[2*p][0], Bh[2*p][1], Bh[2*p+1][0], Bh[2*p+1][1], ba);
                ldsm4(Bl[2*p][0], Bl[2*p][1], Bl[2*p+1][0], Bl[2*p+1][1], ba + (BLO - BHI));
            }
            #pragma unroll
            for (int mt = 0; mt < 4; mt++) {
                const int r = arow + mt * 16;
                const uint32_t aa = smb + AHI + r * 64 +
                    ((uint32_t)((kk * 2 + acsel) ^ ((r >> 1) & 3)) << 4);
                uint32_t Ah[4], Al[4];
                ldsm4(Ah[0], Ah[1], Ah[2], Ah[3], aa);
                ldsm4(Al[0], Al[1], Al[2], Al[3], aa + (ALO - AHI));
                #pragma unroll
                for (int nt = 0; nt < NT; nt++) {
                    mma16816(acc[mt][nt], Ah, Bh[nt]);
                    mma16816(acc[mt][nt], Al, Bh[nt]);
                    mma16816(acc[mt][nt], Ah, Bl[nt]);
                }
            }
        }
        __syncthreads();
    }

    // ---------------- epilogue ----------------
    if constexpr (MODE <= 2) {
        constexpr int P = 132;
        float* stage = (float*)smp;
        #pragma unroll
        for (int mt = 0; mt < 4; mt++) {
            const int rl = wm + mt * 16 + (lane >> 2);
            #pragma unroll
            for (int nt = 0; nt < NT; nt++) {
                const int cl = wn + nt * 8 + (lane & 3) * 2;
                const float2 bb = *(const float2*)&bias[bn0 + cl];
                float2 v0 = { acc[mt][nt][0] + bb.x, acc[mt][nt][1] + bb.y };
                float2 v1 = { acc[mt][nt][2] + bb.x, acc[mt][nt][3] + bb.y };
                *(float2*)&stage[rl * P + cl] = v0;
                *(float2*)&stage[(rl + 8) * P + cl] = v1;
            }
        }
        __syncthreads();
        float* dst = (MODE == 0) ? g_Qh : ((MODE == 1) ? g_Kh : g_Vt);
        if constexpr (MODE <= 1) {
            #pragma unroll
            for (int i = 0; i < 16; i++) {
                const int q = t + 256 * i;
                const int d4 = q & 15, r = (q >> 4) & 31, n = (q >> 9) & 3, hh = q >> 11;
                const float4 v = *(float4*)&stage[(4 * r + n) * P + hh * 64 + d4 * 4];
                const int h = (bn0 >> 6) + hh;
                const size_t a = (((size_t)(n * NHEAD + h) * LLEN) + (bm0 >> 2) + r) * DHEAD + d4 * 4;
                *(float4*)&dst[a] = v;
            }
        } else {
            #pragma unroll
            for (int i = 0; i < 16; i++) {
                const int q = t + 256 * i;
                const int s4 = q & 7, d = (q >> 3) & 63, n = (q >> 9) & 3, hh = q >> 11;
                float4 v;
                v.x = stage[(4 * (s4 * 4 + 0) + n) * P + hh * 64 + d];
                v.y = stage[(4 * (s4 * 4 + 1) + n) * P + hh * 64 + d];
                v.z = stage[(4 * (s4 * 4 + 2) + n) * P + hh * 64 + d];
                v.w = stage[(4 * (s4 * 4 + 3) + n) * P + hh * 64 + d];
                const int h = (bn0 >> 6) + hh;
                const size_t a = ((size_t)(n * NHEAD + h) * DHEAD + d) * SLEN + (bm0 >> 2) + s4 * 4;
                *(float4*)&dst[a] = v;
            }
        }
    } else if constexpr (MODE == 3) {
        #pragma unroll
        for (int mt = 0; mt < 4; mt++) {
            const int r = bm0 + wm + mt * 16 + (lane >> 2);
            #pragma unroll
            for (int nt = 0; nt < NT; nt++) {
                const int cc = bn0 + wn + nt * 8 + (lane & 3) * 2;
                float* d0 = g_scores + (size_t)z * LLEN * SLEN + (size_t)r * SLEN + cc;
                float2 v0 = { acc[mt][nt][0] * 0.125f, acc[mt][nt][1] * 0.125f };
                float2 v1 = { acc[mt][nt][2] * 0.125f, acc[mt][nt][3] * 0.125f };
                *(float2*)d0 = v0;
                *(float2*)(d0 + 8 * SLEN) = v1;
            }
        }
    } else if constexpr (MODE == 4) {
        const int n = z >> 4, h = z & 15;
        #pragma unroll
        for (int mt = 0; mt < 4; mt++) {
            const int r = bm0 + wm + mt * 16 + (lane >> 2);   // l
            #pragma unroll
            for (int nt = 0; nt < NT; nt++) {
                const int cl = wn + nt * 8 + (lane & 3) * 2;  // d within head
                float* d0 = g_ctx + (size_t)r * (NBAT * EDIM) + n * EDIM + h * DHEAD + cl;
                float2 v0 = { acc[mt][nt][0], acc[mt][nt][1] };
                float2 v1 = { acc[mt][nt][2], acc[mt][nt][3] };
                *(float2*)d0 = v0;
                *(float2*)(d0 + 8 * (NBAT * EDIM)) = v1;
            }
        }
    } else {   // MODE 5
        #pragma unroll
        for (int mt = 0; mt < 4; mt++) {
            const int r = bm0 + wm + mt * 16 + (lane >> 2);
            #pragma unroll
            for (int nt = 0; nt < NT; nt++) {
                const int cc = bn0 + wn + nt * 8 + (lane & 3) * 2;
                const float2 bb = *(const float2*)&bias[cc];
                float* d0 = Cout + (size_t)r * EDIM + cc;
                float2 v0 = { acc[mt][nt][0] + bb.x, acc[mt][nt][1] + bb.y };
                float2 v1 = { acc[mt][nt][2] + bb.x, acc[mt][nt][3] + bb.y };
                *(float2*)d0 = v0;
                *(float2*)(d0 + 8 * EDIM) = v1;
            }
        }
    }
}

// ---------------- fast exp on FMA pipe ----------------
__device__ __forceinline__ float fexp(float x)
{
    float y = x * 1.4426950408889634f;
    y = fmaxf(y, -120.0f);
    float r = rintf(y);
    float f = y - r;
    float p = 1.3333558146e-3f;
    p = fmaf(p, f, 9.6181291076e-3f);
    p = fmaf(p, f, 5.5504108665e-2f);
    p = fmaf(p, f, 2.4022650696e-1f);
    p = fmaf(p, f, 6.9314718056e-1f);
    p = fmaf(p, f, 1.0f);
    return p * __int_as_float(((int)r + 127) << 23);
}

// ---------------- fused softmax over 16 heads + head-mean ----------------
__global__ void __launch_bounds__(256)
softmax_mean_k(float* __restrict__ wavg)
{
    const int b = blockIdx.x;
    const int n = b >> 11, l = b & 2047;
    const int t = threadIdx.x;
    __shared__ float sh[8];
    float mean[8];
    #pragma unroll
    for (int i = 0; i < 8; i++) mean[i] = 0.0f;

    for (int h = 0; h < NHEAD; h++) {
        float* row = g_scores + (((size_t)(n * NHEAD + h) * LLEN) + l) * SLEN;
        float x[8];
        #pragma unroll
        for (int i = 0; i < 8; i++) x[i] = row[t + 256 * i];
        float m = x[0];
        #pragma unroll
        for (int i = 1; i < 8; i++) m = fmaxf(m, x[i]);
        #pragma unroll
        for (int o = 16; o > 0; o >>= 1) m = fmaxf(m, __shfl_xor_sync(0xffffffffu, m, o));
        if ((t & 31) == 0) sh[t >> 5] = m;
        __syncthreads();
        m = sh[t & 7];
        #pragma unroll
        for (int o = 4; o > 0; o >>= 1) m = fmaxf(m, __shfl_xor_sync(0xffffffffu, m, o));
        float s = 0.0f;
        #pragma unroll
        for (int i = 0; i < 8; i++) { x[i] = fexp(x[i] - m); s += x[i]; }
        #pragma unroll
        for (int o = 16; o > 0; o >>= 1) s += __shfl_xor_sync(0xffffffffu, s, o);
        __syncthreads();
        if ((t & 31) == 0) sh[t >> 5] = s;
        __syncthreads();
        s = sh[t & 7];
        #pragma unroll
        for (int o = 4; o > 0; o >>= 1) s += __shfl_xor_sync(0xffffffffu, s, o);
        const float inv = 1.0f / s;
        #pragma unroll
        for (int i = 0; i < 8; i++) {
            const float p = x[i] * inv;
            row[t + 256 * i] = p;
            mean[i] += p;
        }
        __syncthreads();
    }
    float* w = wavg + (size_t)b * SLEN;
    #pragma unroll
    for (int i = 0; i < 8; i++) w[t + 256 * i] = mean[i] * 0.0625f;
}

// ---------------- launcher ----------------
extern "C" void kernel_launch(void* const* d_in, const int* in_sizes, int n_in,
                              void* d_out, int out_size)
{
    const float* query = (const float*)d_in[0];
    const float* key   = (const float*)d_in[1];
    const float* value = (const float*)d_in[2];
    const float* Wq = (const float*)d_in[3];  const float* bq = (const float*)d_in[4];
    const float* Wk = (const float*)d_in[5];  const float* bk = (const float*)d_in[6];
    const float* Wv = (const float*)d_in[7];  const float* bv = (const float*)d_in[8];
    const float* Wo = (const float*)d_in[9];  const float* bo = (const float*)d_in[10];
    float* out  = (float*)d_out;
    float* wavg = out + (size_t)LLEN * NBAT * EDIM;

    const int S012 = 69632;   // mainloop 32KB, epilogue stage 128*132*4 = 67584
    const int S35  = 32768;
    const int S4   = 24576;
    cudaFuncSetAttribute(mma_gemm<0>, cudaFuncAttributeMaxDynamicSharedMemorySize, S012);
    cudaFuncSetAttribute(mma_gemm<1>, cudaFuncAttributeMaxDynamicSharedMemorySize, S012);
    cudaFuncSetAttribute(mma_gemm<2>, cudaFuncAttributeMaxDynamicSharedMemorySize, S012);
    cudaFuncSetAttribute(mma_gemm<3>, cudaFuncAttributeMaxDynamicSharedMemorySize, S35);
    cudaFuncSetAttribute(mma_gemm<4>, cudaFuncAttributeMaxDynamicSharedMemorySize, S4);
    cudaFuncSetAttribute(mma_gemm<5>, cudaFuncAttributeMaxDynamicSharedMemorySize, S35);

    dim3 thr(256);
    mma_gemm<0><<<dim3(8, 64, 1),   thr, S012>>>(query, Wq, bq, nullptr);
    mma_gemm<1><<<dim3(8, 64, 1),   thr, S012>>>(key,   Wk, bk, nullptr);
    mma_gemm<2><<<dim3(8, 64, 1),   thr, S012>>>(value, Wv, bv, nullptr);
    mma_gemm<3><<<dim3(16, 16, 64), thr, S35 >>>(nullptr, nullptr, nullptr, nullptr);
    softmax_mean_k<<<NBAT * LLEN, thr>>>(wavg);
    mma_gemm<4><<<dim3(1, 16, 64),  thr, S4  >>>(nullptr, nullptr, nullptr, nullptr);
    mma_gemm<5><<<dim3(8, 64, 1),   thr, S35 >>>(nullptr, Wo, bo, out);
}

// round 8
// speedup vs baseline: 2.5821x; 1.0555x over previous
#include <cuda_runtime.h>
#include <cuda_bf16.h>
#include <cstdint>

#define LLEN 2048
#define SLEN 2048
#define NBAT 4
#define EDIM 1024
#define NHEAD 16
#define DHEAD 64

// ---------------- device scratch (allocation-free rule; < 2GB total) -------
// Q/K/V stored pre-split as bf16 hi/lo pairs (x = hi + lo, fp32-grade).
__device__ __nv_bfloat16 g_Qhi[(size_t)NBAT*NHEAD*LLEN*DHEAD];  // [n,h,l,d]
__device__ __nv_bfloat16 g_Qlo[(size_t)NBAT*NHEAD*LLEN*DHEAD];
__device__ __nv_bfloat16 g_Khi[(size_t)NBAT*NHEAD*SLEN*DHEAD];  // [n,h,s,d]
__device__ __nv_bfloat16 g_Klo[(size_t)NBAT*NHEAD*SLEN*DHEAD];
__device__ __nv_bfloat16 g_Vhi[(size_t)NBAT*NHEAD*DHEAD*SLEN];  // [n,h,d,s]
__device__ __nv_bfloat16 g_Vlo[(size_t)NBAT*NHEAD*DHEAD*SLEN];
// scores hi/lo -> overwritten in place by probs hi/lo after softmax
__device__ __nv_bfloat16 g_Shi[(size_t)NBAT*NHEAD*LLEN*SLEN];   // [n,h,l,s]
__device__ __nv_bfloat16 g_Slo[(size_t)NBAT*NHEAD*LLEN*SLEN];
__device__ float         g_ctx[(size_t)LLEN*NBAT*EDIM];         // [l,n,e]

// ---------------- helpers ----------------
__device__ __forceinline__ uint32_t smem_u32(const void* p) {
    uint32_t a;
    asm("{ .reg .u64 t; cvta.to.shared.u64 t, %1; cvt.u32.u64 %0, t; }" : "=r"(a) : "l"(p));
    return a;
}
// bf16x2: elem0 (low 16b) = cvt(a), elem1 (high 16b) = cvt(b)
__device__ __forceinline__ uint32_t bfpack(float a, float b) {
    uint32_t r;
    asm("cvt.rn.bf16x2.f32 %0, %1, %2;" : "=r"(r) : "f"(b), "f"(a));
    return r;
}
__device__ __forceinline__ float2 bfunpack2(uint32_t p) {
    float2 r;
    r.x = __uint_as_float(p << 16);
    r.y = __uint_as_float(p & 0xffff0000u);
    return r;
}
__device__ __forceinline__ float bfhi(float x) {
    return __bfloat162float(__float2bfloat16(x));
}
__device__ __forceinline__ void ldsm4(uint32_t& r0, uint32_t& r1, uint32_t& r2, uint32_t& r3,
                                      uint32_t addr) {
    asm volatile("ldmatrix.sync.aligned.m8n8.x4.shared.b16 {%0,%1,%2,%3}, [%4];"
                 : "=r"(r0), "=r"(r1), "=r"(r2), "=r"(r3) : "r"(addr));
}
__device__ __forceinline__ void mma16816(float* c, const uint32_t* a, const uint32_t* b) {
    asm volatile("mma.sync.aligned.m16n8k16.row.col.f32.bf16.bf16.f32 "
                 "{%0,%1,%2,%3}, {%4,%5,%6,%7}, {%8,%9}, {%0,%1,%2,%3};"
                 : "+f"(c[0]), "+f"(c[1]), "+f"(c[2]), "+f"(c[3])
                 : "r"(a[0]), "r"(a[1]), "r"(a[2]), "r"(a[3]), "r"(b[0]), "r"(b[1]));
}
#define CPA16(sm, gp) asm volatile("cp.async.cg.shared.global [%0], [%1], 16;" :: "r"(sm), "l"(gp))
#define CPCOMMIT()    asm volatile("cp.async.commit_group;" ::: "memory")
#define CPWAIT0()     asm volatile("cp.async.wait_group 0;" ::: "memory")
#define CPWAIT1()     asm volatile("cp.async.wait_group 1;" ::: "memory")

// fp32 -> bf16 hi/lo split chunk loader (projection / out-proj path)
// ROWS x 32-float K-major chunk; 64B smem rows, swizzle kc ^ ((r>>1)&3)
template<int ROWS, int KP>
__device__ __forceinline__ void load_chunk(char* smp, uint32_t hiOff, uint32_t loOff,
                                           const float* __restrict__ src, int t)
{
    #pragma unroll
    for (int i = 0; i < ROWS / 64; i++) {
        const int idx = t + 256 * i;
        const int r = idx >> 2, kc = idx & 3;
        const float* g = src + (size_t)r * KP + kc * 8;
        const float4 v0 = *(const float4*)g;
        const float4 v1 = *(const float4*)(g + 4);
        float f[8] = { v0.x, v0.y, v0.z, v0.w, v1.x, v1.y, v1.z, v1.w };
        float h[8], l[8];
        #pragma unroll
        for (int j = 0; j < 8; j++) { h[j] = bfhi(f[j]); l[j] = f[j] - h[j]; }
        uint4 h4, l4;
        h4.x = bfpack(h[0], h[1]); h4.y = bfpack(h[2], h[3]);
        h4.z = bfpack(h[4], h[5]); h4.w = bfpack(h[6], h[7]);
        l4.x = bfpack(l[0], l[1]); l4.y = bfpack(l[2], l[3]);
        l4.z = bfpack(l[4], l[5]); l4.w = bfpack(l[6], l[7]);
        const uint32_t off = r * 64 + ((uint32_t)(kc ^ ((r >> 1) & 3)) << 4);
        *(uint4*)(smp + hiOff + off) = h4;
        *(uint4*)(smp + loOff + off) = l4;
    }
}

// ---------------------------------------------------------------------------
// Projection / out-proj GEMM (fp32 in). MODE 0: Q, 1: K, 2: V, 5: out proj.
// ---------------------------------------------------------------------------
template<int MODE>
__global__ void __launch_bounds__(256, 2)
mma_gemm(const float* __restrict__ Ain, const float* __restrict__ Bin,
         const float* __restrict__ bias, float* __restrict__ Cout)
{
    constexpr int KK = 1024, NC = KK / 32;
    constexpr uint32_t AHI = 0, ALO = 8192, BHI = 16384, BLO = 24576;

    extern __shared__ char smp[];
    const int t = threadIdx.x, lane = t & 31, wid = t >> 5;
    const int wm = (wid >> 2) * 64;
    const int wn = (wid & 3) * 32;
    const int bm0 = blockIdx.y * 128, bn0 = blockIdx.x * 128;

    const float* Asrc = ((MODE == 5) ? g_ctx : Ain) + (size_t)bm0 * KK;
    const float* Bsrc = Bin + (size_t)bn0 * KK;

    float acc[4][4][4];
    #pragma unroll
    for (int m = 0; m < 4; m++)
        #pragma unroll
        for (int n = 0; n < 4; n++)
            #pragma unroll
            for (int v = 0; v < 4; v++) acc[m][n][v] = 0.0f;

    const int arow  = wm + ((lane >> 3) & 1) * 8 + (lane & 7);
    const int acsel = lane >> 4;
    const int brow  = wn + (lane >> 4) * 8 + (lane & 7);
    const int bcsel = (lane >> 3) & 1;
    const uint32_t smb = smem_u32(smp);

    for (int c = 0; c < NC; c++) {
        load_chunk<128, KK>(smp, AHI, ALO, Asrc + c * 32, t);
        load_chunk<128, KK>(smp, BHI, BLO, Bsrc + c * 32, t);
        __syncthreads();
        #pragma unroll
        for (int kk = 0; kk < 2; kk++) {
            uint32_t Bh[4][2], Bl[4][2];
            #pragma unroll
            for (int p = 0; p < 2; p++) {
                const int r = brow + p * 16;
                const uint32_t ba = smb + BHI + r * 64 +
                    ((uint32_t)((kk * 2 + bcsel) ^ ((r >> 1) & 3)) << 4);
                ldsm4(Bh[2*p][0], Bh[2*p][1], Bh[2*p+1][0], Bh[2*p+1][1], ba);
                ldsm4(Bl[2*p][0], Bl[2*p][1], Bl[2*p+1][0], Bl[2*p+1][1], ba + (BLO - BHI));
            }
            #pragma unroll
            for (int mt = 0; mt < 4; mt++) {
                const int r = arow + mt * 16;
                const uint32_t aa = smb + AHI + r * 64 +
                    ((uint32_t)((kk * 2 + acsel) ^ ((r >> 1) & 3)) << 4);
                uint32_t Ah[4], Al[4];
                ldsm4(Ah[0], Ah[1], Ah[2], Ah[3], aa);
                ldsm4(Al[0], Al[1], Al[2], Al[3], aa + (ALO - AHI));
                #pragma unroll
                for (int nt = 0; nt < 4; nt++) {
                    mma16816(acc[mt][nt], Ah, Bh[nt]);
                    mma16816(acc[mt][nt], Al, Bh[nt]);
                    mma16816(acc[mt][nt], Ah, Bl[nt]);
                }
            }
        }
        __syncthreads();
    }

    if constexpr (MODE == 5) {
        #pragma unroll
        for (int mt = 0; mt < 4; mt++) {
            const int r = bm0 + wm + mt * 16 + (lane >> 2);
            #pragma unroll
            for (int nt = 0; nt < 4; nt++) {
                const int cc = bn0 + wn + nt * 8 + (lane & 3) * 2;
                const float2 bb = *(const float2*)&bias[cc];
                float* d0 = Cout + (size_t)r * EDIM + cc;
                float2 v0 = { acc[mt][nt][0] + bb.x, acc[mt][nt][1] + bb.y };
                float2 v1 = { acc[mt][nt][2] + bb.x, acc[mt][nt][3] + bb.y };
                *(float2*)d0 = v0;
                *(float2*)(d0 + 8 * EDIM) = v1;
            }
        }
    } else {
        // stage fp32 (with bias) then scatter as bf16 hi/lo into head layouts
        constexpr int P = 132;
        float* stage = (float*)smp;
        #pragma unroll
        for (int mt = 0; mt < 4; mt++) {
            const int rl = wm + mt * 16 + (lane >> 2);
            #pragma unroll
            for (int nt = 0; nt < 4; nt++) {
                const int cl = wn + nt * 8 + (lane & 3) * 2;
                const float2 bb = *(const float2*)&bias[bn0 + cl];
                float2 v0 = { acc[mt][nt][0] + bb.x, acc[mt][nt][1] + bb.y };
                float2 v1 = { acc[mt][nt][2] + bb.x, acc[mt][nt][3] + bb.y };
                *(float2*)&stage[rl * P + cl] = v0;
                *(float2*)&stage[(rl + 8) * P + cl] = v1;
            }
        }
        __syncthreads();
        __nv_bfloat16* dh = (MODE == 0) ? g_Qhi : ((MODE == 1) ? g_Khi : g_Vhi);
        __nv_bfloat16* dl = (MODE == 0) ? g_Qlo : ((MODE == 1) ? g_Klo : g_Vlo);
        if constexpr (MODE <= 1) {
            #pragma unroll
            for (int i = 0; i < 16; i++) {
                const int q = t + 256 * i;
                const int d4 = q & 15, r = (q >> 4) & 31, n = (q >> 9) & 3, hh = q >> 11;
                const float4 v = *(float4*)&stage[(4 * r + n) * P + hh * 64 + d4 * 4];
                const float h0 = bfhi(v.x), h1 = bfhi(v.y), h2 = bfhi(v.z), h3 = bfhi(v.w);
                uint2 hp = { bfpack(h0, h1), bfpack(h2, h3) };
                uint2 lp = { bfpack(v.x - h0, v.y - h1), bfpack(v.z - h2, v.w - h3) };
                const int hd = (bn0 >> 6) + hh;
                const size_t a = (((size_t)(n * NHEAD + hd) * LLEN) + (bm0 >> 2) + r) * DHEAD + d4 * 4;
                *(uint2*)(dh + a) = hp;
                *(uint2*)(dl + a) = lp;
            }
        } else {
            #pragma unroll
            for (int i = 0; i < 16; i++) {
                const int q = t + 256 * i;
                const int s4 = q & 7, d = (q >> 3) & 63, n = (q >> 9) & 3, hh = q >> 11;
                float4 v;
                v.x = stage[(4 * (s4 * 4 + 0) + n) * P + hh * 64 + d];
                v.y = stage[(4 * (s4 * 4 + 1) + n) * P + hh * 64 + d];
                v.z = stage[(4 * (s4 * 4 + 2) + n) * P + hh * 64 + d];
                v.w = stage[(4 * (s4 * 4 + 3) + n) * P + hh * 64 + d];
                const float h0 = bfhi(v.x), h1 = bfhi(v.y), h2 = bfhi(v.z), h3 = bfhi(v.w);
                uint2 hp = { bfpack(h0, h1), bfpack(h2, h3) };
                uint2 lp = { bfpack(v.x - h0, v.y - h1), bfpack(v.z - h2, v.w - h3) };
                const int hd = (bn0 >> 6) + hh;
                const size_t a = ((size_t)(n * NHEAD + hd) * DHEAD + d) * SLEN + (bm0 >> 2) + s4 * 4;
                *(uint2*)(dh + a) = hp;
                *(uint2*)(dl + a) = lp;
            }
        }
    }
}

// ---------------------------------------------------------------------------
// Scores GEMM: per z=(n,h): S = Qz[2048,64] @ Kz[2048,64]^T * 0.125
// -> bf16 hi/lo logits (g_Shi/g_Slo). Pre-split bf16 inputs; one cp.async
// burst covers the whole K=64. smem: 128B rows, swizzle kc ^ (r&7).
// ---------------------------------------------------------------------------
__global__ void __launch_bounds__(256, 2)
qk_gemm()
{
    constexpr uint32_t AHI = 0, ALO = 16384, BHI = 32768, BLO = 49152;
    extern __shared__ char smp[];
    const int t = threadIdx.x, lane = t & 31, wid = t >> 5;
    const int wm = (wid >> 2) * 64, wn = (wid & 3) * 32;
    const int bm0 = blockIdx.y * 128, bn0 = blockIdx.x * 128, z = blockIdx.z;
    const uint32_t smb = smem_u32(smp);

    const __nv_bfloat16* Ahg = g_Qhi + (size_t)z * LLEN * DHEAD + (size_t)bm0 * 64;
    const __nv_bfloat16* Alg = g_Qlo + (size_t)z * LLEN * DHEAD + (size_t)bm0 * 64;
    const __nv_bfloat16* Bhg = g_Khi + (size_t)z * SLEN * DHEAD + (size_t)bn0 * 64;
    const __nv_bfloat16* Blg = g_Klo + (size_t)z * SLEN * DHEAD + (size_t)bn0 * 64;

    #pragma unroll
    for (int i = 0; i < 4; i++) {
        const int idx = t + 256 * i;
        const int r = idx >> 3, kc = idx & 7;
        const uint32_t so = r * 128 + ((uint32_t)(kc ^ (r & 7)) << 4);
        const size_t go = (size_t)r * 64 + kc * 8;
        CPA16(smb + AHI + so, Ahg + go);
        CPA16(smb + ALO + so, Alg + go);
        CPA16(smb + BHI + so, Bhg + go);
        CPA16(smb + BLO + so, Blg + go);
    }
    CPCOMMIT(); CPWAIT0();
    __syncthreads();

    float acc[4][4][4];
    #pragma unroll
    for (int m = 0; m < 4; m++)
        #pragma unroll
        for (int n = 0; n < 4; n++)
            #pragma unroll
            for (int v = 0; v < 4; v++) acc[m][n][v] = 0.0f;

    const int arow  = wm + ((lane >> 3) & 1) * 8 + (lane & 7);
    const int acsel = lane >> 4;
    const int brow  = wn + (lane >> 4) * 8 + (lane & 7);
    const int bcsel = (lane >> 3) & 1;

    #pragma unroll
    for (int kk = 0; kk < 4; kk++) {
        uint32_t Bh[4][2], Bl[4][2];
        #pragma unroll
        for (int p = 0; p < 2; p++) {
            const int r = brow + p * 16, kc = kk * 2 + bcsel;
            const uint32_t ba = smb + BHI + r * 128 + ((uint32_t)(kc ^ (r & 7)) << 4);
            ldsm4(Bh[2*p][0], Bh[2*p][1], Bh[2*p+1][0], Bh[2*p+1][1], ba);
            ldsm4(Bl[2*p][0], Bl[2*p][1], Bl[2*p+1][0], Bl[2*p+1][1], ba + (BLO - BHI));
        }
        #pragma unroll
        for (int mt = 0; mt < 4; mt++) {
            const int r = arow + mt * 16, kc = kk * 2 + acsel;
            const uint32_t aa = smb + AHI + r * 128 + ((uint32_t)(kc ^ (r & 7)) << 4);
            uint32_t Ah[4], Al[4];
            ldsm4(Ah[0], Ah[1], Ah[2], Ah[3], aa);
            ldsm4(Al[0], Al[1], Al[2], Al[3], aa + (ALO - AHI));
            #pragma unroll
            for (int nt = 0; nt < 4; nt++) {
                mma16816(acc[mt][nt], Ah, Bh[nt]);
                mma16816(acc[mt][nt], Al, Bh[nt]);
                mma16816(acc[mt][nt], Ah, Bl[nt]);
            }
        }
    }

    #pragma unroll
    for (int mt = 0; mt < 4; mt++) {
        const int r = bm0 + wm + mt * 16 + (lane >> 2);
        #pragma unroll
        for (int nt = 0; nt < 4; nt++) {
            const int cc = bn0 + wn + nt * 8 + (lane & 3) * 2;
            const size_t e0 = (size_t)z * LLEN * SLEN + (size_t)r * SLEN + cc;
            const size_t e1 = e0 + 8 * SLEN;
            float v0x = acc[mt][nt][0] * 0.125f, v0y = acc[mt][nt][1] * 0.125f;
            float v1x = acc[mt][nt][2] * 0.125f, v1y = acc[mt][nt][3] * 0.125f;
            const float h0x = bfhi(v0x), h0y = bfhi(v0y);
            const float h1x = bfhi(v1x), h1y = bfhi(v1y);
            *(uint32_t*)(g_Shi + e0) = bfpack(h0x, h0y);
            *(uint32_t*)(g_Slo + e0) = bfpack(v0x - h0x, v0y - h0y);
            *(uint32_t*)(g_Shi + e1) = bfpack(h1x, h1y);
            *(uint32_t*)(g_Slo + e1) = bfpack(v1x - h1x, v1y - h1y);
        }
    }
}

// ---------------------------------------------------------------------------
// P @ V GEMM: per z: ctx = P[2048,2048] @ Vt[64,2048]^T -> g_ctx scatter.
// Probs hi/lo read from g_Shi/g_Slo (in-place after softmax).
// 2-stage cp.async pipeline. smem: 64B rows, swizzle kc ^ ((r>>1)&3).
// ---------------------------------------------------------------------------
__global__ void __launch_bounds__(256, 2)
pv_gemm()
{
    constexpr int NC = 64;
    constexpr uint32_t STG = 24576, AHI = 0, ALO = 8192, BHI = 16384, BLO = 20480;
    extern __shared__ char smp[];
    const int t = threadIdx.x, lane = t & 31, wid = t >> 5;
    const int wm = (wid >> 2) * 64, wn = (wid & 3) * 16;
    const int bm0 = blockIdx.y * 128, z = blockIdx.z;
    const uint32_t smb = smem_u32(smp);

    const __nv_bfloat16* Ahg = g_Shi + (size_t)z * LLEN * SLEN + (size_t)bm0 * 2048;
    const __nv_bfloat16* Alg = g_Slo + (size_t)z * LLEN * SLEN + (size_t)bm0 * 2048;
    const __nv_bfloat16* Bhg = g_Vhi + (size_t)z * DHEAD * SLEN;
    const __nv_bfloat16* Blg = g_Vlo + (size_t)z * DHEAD * SLEN;

    auto issue = [&](int c) {
        const uint32_t sb = (uint32_t)(c & 1) * STG;
        #pragma unroll
        for (int i = 0; i < 2; i++) {
            const int idx = t + 256 * i;
            const int r = idx >> 2, kc = idx & 3;
            const uint32_t so = r * 64 + ((uint32_t)(kc ^ ((r >> 1) & 3)) << 4);
            const size_t go = (size_t)r * 2048 + c * 32 + kc * 8;
            CPA16(smb + sb + AHI + so, Ahg + go);
            CPA16(smb + sb + ALO + so, Alg + go);
        }
        {
            const int r = t >> 2, kc = t & 3;   // 64 rows x 4 chunks
            const uint32_t so = r * 64 + ((uint32_t)(kc ^ ((r >> 1) & 3)) << 4);
            const size_t go = (size_t)r * 2048 + c * 32 + kc * 8;
            CPA16(smb + sb + BHI + so, Bhg + go);
            CPA16(smb + sb + BLO + so, Blg + go);
        }
        CPCOMMIT();
    };

    issue(0); issue(1);

    float acc[4][2][4];
    #pragma unroll
    for (int m = 0; m < 4; m++)
        #pragma unroll
        for (int n = 0; n < 2; n++)
            #pragma unroll
            for (int v = 0; v < 4; v++) acc[m][n][v] = 0.0f;

    const int arow  = wm + ((lane >> 3) & 1) * 8 + (lane & 7);
    const int acsel = lane >> 4;
    const int brow  = wn + (lane >> 4) * 8 + (lane & 7);
    const int bcsel = (lane >> 3) & 1;

    for (int c = 0; c < NC; c++) {
        if (c + 1 < NC) { CPWAIT1(); } else { CPWAIT0(); }
        __syncthreads();
        const uint32_t sb = (uint32_t)(c & 1) * STG;
        #pragma unroll
        for (int kk = 0; kk < 2; kk++) {
            uint32_t Bh[2][2], Bl[2][2];
            {
                const int r = brow, kc = kk * 2 + bcsel;
                const uint32_t ba = smb + sb + BHI + r * 64 +
                    ((uint32_t)(kc ^ ((r >> 1) & 3)) << 4);
                ldsm4(Bh[0][0], Bh[0][1], Bh[1][0], Bh[1][1], ba);
                ldsm4(Bl[0][0], Bl[0][1], Bl[1][0], Bl[1][1], ba + (BLO - BHI));
            }
            #pragma unroll
            for (int mt = 0; mt < 4; mt++) {
                const int r = arow + mt * 16, kc = kk * 2 + acsel;
                const uint32_t aa = smb + sb + AHI + r * 64 +
                    ((uint32_t)(kc ^ ((r >> 1) & 3)) << 4);
                uint32_t Ah[4], Al[4];
                ldsm4(Ah[0], Ah[1], Ah[2], Ah[3], aa);
                ldsm4(Al[0], Al[1], Al[2], Al[3], aa + (ALO - AHI));
                #pragma unroll
                for (int nt = 0; nt < 2; nt++) {
                    mma16816(acc[mt][nt], Ah, Bh[nt]);
                    mma16816(acc[mt][nt], Al, Bh[nt]);
                    mma16816(acc[mt][nt], Ah, Bl[nt]);
                }
            }
        }
        __syncthreads();
        if (c + 2 < NC) issue(c + 2);
    }

    const int n = z >> 4, h = z & 15;
    #pragma unroll
    for (int mt = 0; mt < 4; mt++) {
        const int r = bm0 + wm + mt * 16 + (lane >> 2);
        #pragma unroll
        for (int nt = 0; nt < 2; nt++) {
            const int cl = wn + nt * 8 + (lane & 3) * 2;
            float* d0 = g_ctx + (size_t)r * (NBAT * EDIM) + n * EDIM + h * DHEAD + cl;
            float2 v0 = { acc[mt][nt][0], acc[mt][nt][1] };
            float2 v1 = { acc[mt][nt][2], acc[mt][nt][3] };
            *(float2*)d0 = v0;
            *(float2*)(d0 + 8 * (NBAT * EDIM)) = v1;
        }
    }
}

// ---------------- fast exp on FMA pipe ----------------
__device__ __forceinline__ float fexp(float x)
{
    float y = x * 1.4426950408889634f;
    y = fmaxf(y, -120.0f);
    float r = rintf(y);
    float f = y - r;
    float p = 1.3333558146e-3f;
    p = fmaf(p, f, 9.6181291076e-3f);
    p = fmaf(p, f, 5.5504108665e-2f);
    p = fmaf(p, f, 2.4022650696e-1f);
    p = fmaf(p, f, 6.9314718056e-1f);
    p = fmaf(p, f, 1.0f);
    return p * __int_as_float(((int)r + 127) << 23);
}

// ---------------- fused softmax (16 heads) + head-mean; in-place probs ------
__global__ void __launch_bounds__(256)
softmax_mean_k(float* __restrict__ wavg)
{
    const int b = blockIdx.x;
    const int n = b >> 11, l = b & 2047;
    const int t = threadIdx.x;
    __shared__ float sh[8];
    float mean[8];
    #pragma unroll
    for (int i = 0; i < 8; i++) mean[i] = 0.0f;

    for (int h = 0; h < NHEAD; h++) {
        const size_t base = (((size_t)(n * NHEAD + h) * LLEN) + l) * SLEN + (size_t)t * 8;
        const uint4 ph = *(const uint4*)(g_Shi + base);
        const uint4 pl = *(const uint4*)(g_Slo + base);
        float x[8];
        {
            float2 a, c;
            a = bfunpack2(ph.x); c = bfunpack2(pl.x); x[0] = a.x + c.x; x[1] = a.y + c.y;
            a = bfunpack2(ph.y); c = bfunpack2(pl.y); x[2] = a.x + c.x; x[3] = a.y + c.y;
            a = bfunpack2(ph.z); c = bfunpack2(pl.z); x[4] = a.x + c.x; x[5] = a.y + c.y;
            a = bfunpack2(ph.w); c = bfunpack2(pl.w); x[6] = a.x + c.x; x[7] = a.y + c.y;
        }
        float m = x[0];
        #pragma unroll
        for (int i = 1; i < 8; i++) m = fmaxf(m, x[i]);
        #pragma unroll
        for (int o = 16; o > 0; o >>= 1) m = fmaxf(m, __shfl_xor_sync(0xffffffffu, m, o));
        if ((t & 31) == 0) sh[t >> 5] = m;
        __syncthreads();
        m = sh[t & 7];
        #pragma unroll
        for (int o = 4; o > 0; o >>= 1) m = fmaxf(m, __shfl_xor_sync(0xffffffffu, m, o));
        float s = 0.0f;
        #pragma unroll
        for (int i = 0; i < 8; i++) { x[i] = fexp(x[i] - m); s += x[i]; }
        #pragma unroll
        for (int o = 16; o > 0; o >>= 1) s += __shfl_xor_sync(0xffffffffu, s, o);
        __syncthreads();
        if ((t & 31) == 0) sh[t >> 5] = s;
        __syncthreads();
        s = sh[t & 7];
        #pragma unroll
        for (int o = 4; o > 0; o >>= 1) s += __shfl_xor_sync(0xffffffffu, s, o);
        const float inv = 1.0f / s;
        uint4 oh, ol;
        float hx, hy;
        #pragma unroll
        for (int i = 0; i < 8; i++) { x[i] *= inv; mean[i] += x[i]; }
        hx = bfhi(x[0]); hy = bfhi(x[1]);
        oh.x = bfpack(hx, hy); ol.x = bfpack(x[0] - hx, x[1] - hy);
        hx = bfhi(x[2]); hy = bfhi(x[3]);
        oh.y = bfpack(hx, hy); ol.y = bfpack(x[2] - hx, x[3] - hy);
        hx = bfhi(x[4]); hy = bfhi(x[5]);
        oh.z = bfpack(hx, hy); ol.z = bfpack(x[4] - hx, x[5] - hy);
        hx = bfhi(x[6]); hy = bfhi(x[7]);
        oh.w = bfpack(hx, hy); ol.w = bfpack(x[6] - hx, x[7] - hy);
        *(uint4*)(g_Shi + base) = oh;
        *(uint4*)(g_Slo + base) = ol;
        __syncthreads();
    }
    float4* w = (float4*)(wavg + (size_t)b * SLEN + (size_t)t * 8);
    float4 w0 = { mean[0] * 0.0625f, mean[1] * 0.0625f, mean[2] * 0.0625f, mean[3] * 0.0625f };
    float4 w1 = { mean[4] * 0.0625f, mean[5] * 0.0625f, mean[6] * 0.0625f, mean[7] * 0.0625f };
    w[0] = w0;
    w[1] = w1;
}

// ---------------- launcher ----------------
extern "C" void kernel_launch(void* const* d_in, const int* in_sizes, int n_in,
                              void* d_out, int out_size)
{
    const float* query = (const float*)d_in[0];
    const float* key   = (const float*)d_in[1];
    const float* value = (const float*)d_in[2];
    const float* Wq = (const float*)d_in[3];  const float* bq = (const float*)d_in[4];
    const float* Wk = (const float*)d_in[5];  const float* bk = (const float*)d_in[6];
    const float* Wv = (const float*)d_in[7];  const float* bv = (const float*)d_in[8];
    const float* Wo = (const float*)d_in[9];  const float* bo = (const float*)d_in[10];
    float* out  = (float*)d_out;
    float* wavg = out + (size_t)LLEN * NBAT * EDIM;

    const int S012 = 69632;   // mainloop 32KB; epilogue stage 128*132*4 = 67584
    const int S5   = 32768;
    const int SQK  = 65536;
    const int SPV  = 49152;
    cudaFuncSetAttribute(mma_gemm<0>, cudaFuncAttributeMaxDynamicSharedMemorySize, S012);
    cudaFuncSetAttribute(mma_gemm<1>, cudaFuncAttributeMaxDynamicSharedMemorySize, S012);
    cudaFuncSetAttribute(mma_gemm<2>, cudaFuncAttributeMaxDynamicSharedMemorySize, S012);
    cudaFuncSetAttribute(mma_gemm<5>, cudaFuncAttributeMaxDynamicSharedMemorySize, S5);
    cudaFuncSetAttribute(qk_gemm,     cudaFuncAttributeMaxDynamicSharedMemorySize, SQK);
    cudaFuncSetAttribute(pv_gemm,     cudaFuncAttributeMaxDynamicSharedMemorySize, SPV);

    dim3 thr(256);
    mma_gemm<0><<<dim3(8, 64, 1), thr, S012>>>(query, Wq, bq, nullptr);
    mma_gemm<1><<<dim3(8, 64, 1), thr, S012>>>(key,   Wk, bk, nullptr);
    mma_gemm<2><<<dim3(8, 64, 1), thr, S012>>>(value, Wv, bv, nullptr);
    qk_gemm<<<dim3(16, 16, 64), thr, SQK>>>();
    softmax_mean_k<<<NBAT * LLEN, thr>>>(wavg);
    pv_gemm<<<dim3(1, 16, 64), thr, SPV>>>();
    mma_gemm<5><<<dim3(8, 64, 1), thr, S5>>>(nullptr, Wo, bo, out);
}

// round 11
// speedup vs baseline: 2.7203x; 1.0535x over previous
#include <cuda_runtime.h>
#include <cuda_bf16.h>
#include <cstdint>

#define LLEN 2048
#define SLEN 2048
#define NBAT 4
#define EDIM 1024
#define NHEAD 16
#define DHEAD 64

// ---------------- device scratch (allocation-free rule; < 2GB total) -------
// Q/K/V stored pre-split as bf16 hi/lo pairs (x = hi + lo, fp32-grade).
// Q is pre-scaled by 0.125 (= 1/sqrt(64)).
__device__ __nv_bfloat16 g_Qhi[(size_t)NBAT*NHEAD*LLEN*DHEAD];  // [n,h,l,d]
__device__ __nv_bfloat16 g_Qlo[(size_t)NBAT*NHEAD*LLEN*DHEAD];
__device__ __nv_bfloat16 g_Khi[(size_t)NBAT*NHEAD*SLEN*DHEAD];  // [n,h,s,d]
__device__ __nv_bfloat16 g_Klo[(size_t)NBAT*NHEAD*SLEN*DHEAD];
__device__ __nv_bfloat16 g_Vhi[(size_t)NBAT*NHEAD*DHEAD*SLEN];  // [n,h,d,s]
__device__ __nv_bfloat16 g_Vlo[(size_t)NBAT*NHEAD*DHEAD*SLEN];
// scores hi/lo -> overwritten in place by probs hi/lo after softmax
__device__ __nv_bfloat16 g_Shi[(size_t)NBAT*NHEAD*LLEN*SLEN];   // [n,h,l,s]
__device__ __nv_bfloat16 g_Slo[(size_t)NBAT*NHEAD*LLEN*SLEN];
__device__ float         g_ctx[(size_t)LLEN*NBAT*EDIM];         // [l,n,e]

// ---------------- helpers ----------------
__device__ __forceinline__ uint32_t smem_u32(const void* p) {
    uint32_t a;
    asm("{ .reg .u64 t; cvta.to.shared.u64 t, %1; cvt.u32.u64 %0, t; }" : "=r"(a) : "l"(p));
    return a;
}
// bf16x2: elem0 (low 16b) = cvt(a), elem1 (high 16b) = cvt(b)
__device__ __forceinline__ uint32_t bfpack(float a, float b) {
    uint32_t r;
    asm("cvt.rn.bf16x2.f32 %0, %1, %2;" : "=r"(r) : "f"(b), "f"(a));
    return r;
}
__device__ __forceinline__ float2 bfunpack2(uint32_t p) {
    float2 r;
    r.x = __uint_as_float(p << 16);
    r.y = __uint_as_float(p & 0xffff0000u);
    return r;
}
__device__ __forceinline__ float bfhi(float x) {
    return __bfloat162float(__float2bfloat16(x));
}
__device__ __forceinline__ void ldsm4(uint32_t& r0, uint32_t& r1, uint32_t& r2, uint32_t& r3,
                                      uint32_t addr) {
    asm volatile("ldmatrix.sync.aligned.m8n8.x4.shared.b16 {%0,%1,%2,%3}, [%4];"
                 : "=r"(r0), "=r"(r1), "=r"(r2), "=r"(r3) : "r"(addr));
}
__device__ __forceinline__ void mma16816(float* c, const uint32_t* a, const uint32_t* b) {
    asm volatile("mma.sync.aligned.m16n8k16.row.col.f32.bf16.bf16.f32 "
                 "{%0,%1,%2,%3}, {%4,%5,%6,%7}, {%8,%9}, {%0,%1,%2,%3};"
                 : "+f"(c[0]), "+f"(c[1]), "+f"(c[2]), "+f"(c[3])
                 : "r"(a[0]), "r"(a[1]), "r"(a[2]), "r"(a[3]), "r"(b[0]), "r"(b[1]));
}
#define CPA16(sm, gp) asm volatile("cp.async.cg.shared.global [%0], [%1], 16;" :: "r"(sm), "l"(gp))
#define CPCOMMIT()    asm volatile("cp.async.commit_group;" ::: "memory")
#define CPWAIT0()     asm volatile("cp.async.wait_group 0;" ::: "memory")
#define CPWAIT1()     asm volatile("cp.async.wait_group 1;" ::: "memory")

// fp32 -> bf16 hi/lo split chunk loader; 64B smem rows, swizzle kc ^ ((r>>1)&3)
template<int ROWS, int KP>
__device__ __forceinline__ void load_chunk(char* smp, uint32_t hiOff, uint32_t loOff,
                                           const float* __restrict__ src, int t)
{
    #pragma unroll
    for (int i = 0; i < ROWS / 64; i++) {
        const int idx = t + 256 * i;
        const int r = idx >> 2, kc = idx & 3;
        const float* g = src + (size_t)r * KP + kc * 8;
        const float4 v0 = *(const float4*)g;
        const float4 v1 = *(const float4*)(g + 4);
        float f[8] = { v0.x, v0.y, v0.z, v0.w, v1.x, v1.y, v1.z, v1.w };
        float h[8], l[8];
        #pragma unroll
        for (int j = 0; j < 8; j++) { h[j] = bfhi(f[j]); l[j] = f[j] - h[j]; }
        uint4 h4, l4;
        h4.x = bfpack(h[0], h[1]); h4.y = bfpack(h[2], h[3]);
        h4.z = bfpack(h[4], h[5]); h4.w = bfpack(h[6], h[7]);
        l4.x = bfpack(l[0], l[1]); l4.y = bfpack(l[2], l[3]);
        l4.z = bfpack(l[4], l[5]); l4.w = bfpack(l[6], l[7]);
        const uint32_t off = r * 64 + ((uint32_t)(kc ^ ((r >> 1) & 3)) << 4);
        *(uint4*)(smp + hiOff + off) = h4;
        *(uint4*)(smp + loOff + off) = l4;
    }
}

// ---------------------------------------------------------------------------
// Fused Q/K/V projection GEMM (z = blockIdx.z selects 0:Q 1:K 2:V).
// C = X[8192,1024] @ W^T (+bias); Q additionally scaled by 0.125.
// Scatter to pre-split bf16 head layouts.
// ---------------------------------------------------------------------------
__global__ void __launch_bounds__(256, 2)
qkv_gemm(const float* __restrict__ query, const float* __restrict__ key,
         const float* __restrict__ value,
         const float* __restrict__ Wq, const float* __restrict__ Wk,
         const float* __restrict__ Wv,
         const float* __restrict__ bq, const float* __restrict__ bk,
         const float* __restrict__ bv)
{
    constexpr int KK = 1024, NC = KK / 32;
    constexpr uint32_t AHI = 0, ALO = 8192, BHI = 16384, BLO = 24576;

    extern __shared__ char smp[];
    const int t = threadIdx.x, lane = t & 31, wid = t >> 5;
    const int wm = (wid >> 2) * 64;
    const int wn = (wid & 3) * 32;
    const int bm0 = blockIdx.y * 128, bn0 = blockIdx.x * 128, z = blockIdx.z;

    const float* Ain  = (z == 0) ? query : ((z == 1) ? key : value);
    const float* Bin  = (z == 0) ? Wq : ((z == 1) ? Wk : Wv);
    const float* bias = (z == 0) ? bq : ((z == 1) ? bk : bv);
    const float  sc   = (z == 0) ? 0.125f : 1.0f;

    const float* Asrc = Ain + (size_t)bm0 * KK;
    const float* Bsrc = Bin + (size_t)bn0 * KK;

    float acc[4][4][4];
    #pragma unroll
    for (int m = 0; m < 4; m++)
        #pragma unroll
        for (int n = 0; n < 4; n++)
            #pragma unroll
            for (int v = 0; v < 4; v++) acc[m][n][v] = 0.0f;

    const int arow  = wm + ((lane >> 3) & 1) * 8 + (lane & 7);
    const int acsel = lane >> 4;
    const int brow  = wn + (lane >> 4) * 8 + (lane & 7);
    const int bcsel = (lane >> 3) & 1;
    const uint32_t smb = smem_u32(smp);

    for (int c = 0; c < NC; c++) {
        load_chunk<128, KK>(smp, AHI, ALO, Asrc + c * 32, t);
        load_chunk<128, KK>(smp, BHI, BLO, Bsrc + c * 32, t);
        __syncthreads();
        #pragma unroll
        for (int kk = 0; kk < 2; kk++) {
            uint32_t Bh[4][2], Bl[4][2];
            #pragma unroll
            for (int p = 0; p < 2; p++) {
                const int r = brow + p * 16;
                const uint32_t ba = smb + BHI + r * 64 +
                    ((uint32_t)((kk * 2 + bcsel) ^ ((r >> 1) & 3)) << 4);
                ldsm4(Bh[2*p][0], Bh[2*p][1], Bh[2*p+1][0], Bh[2*p+1][1], ba);
                ldsm4(Bl[2*p][0], Bl[2*p][1], Bl[2*p+1][0], Bl[2*p+1][1], ba + (BLO - BHI));
            }
            #pragma unroll
            for (int mt = 0; mt < 4; mt++) {
                const int r = arow + mt * 16;
                const uint32_t aa = smb + AHI + r * 64 +
                    ((uint32_t)((kk * 2 + acsel) ^ ((r >> 1) & 3)) << 4);
                uint32_t Ah[4], Al[4];
                ldsm4(Ah[0], Ah[1], Ah[2], Ah[3], aa);
                ldsm4(Al[0], Al[1], Al[2], Al[3], aa + (ALO - AHI));
                #pragma unroll
                for (int nt = 0; nt < 4; nt++) {
                    mma16816(acc[mt][nt], Ah, Bh[nt]);
                    mma16816(acc[mt][nt], Al, Bh[nt]);
                    mma16816(acc[mt][nt], Ah, Bl[nt]);
                }
            }
        }
        __syncthreads();
    }

    // stage fp32 (with bias, scale) then scatter bf16 hi/lo into head layouts
    constexpr int P = 132;
    float* stage = (float*)smp;
    #pragma unroll
    for (int mt = 0; mt < 4; mt++) {
        const int rl = wm + mt * 16 + (lane >> 2);
        #pragma unroll
        for (int nt = 0; nt < 4; nt++) {
            const int cl = wn + nt * 8 + (lane & 3) * 2;
            const float2 bb = *(const float2*)&bias[bn0 + cl];
            float2 v0 = { (acc[mt][nt][0] + bb.x) * sc, (acc[mt][nt][1] + bb.y) * sc };
            float2 v1 = { (acc[mt][nt][2] + bb.x) * sc, (acc[mt][nt][3] + bb.y) * sc };
            *(float2*)&stage[rl * P + cl] = v0;
            *(float2*)&stage[(rl + 8) * P + cl] = v1;
        }
    }
    __syncthreads();
    if (z <= 1) {
        __nv_bfloat16* dh = (z == 0) ? g_Qhi : g_Khi;
        __nv_bfloat16* dl = (z == 0) ? g_Qlo : g_Klo;
        #pragma unroll
        for (int i = 0; i < 16; i++) {
            const int q = t + 256 * i;
            const int d4 = q & 15, r = (q >> 4) & 31, n = (q >> 9) & 3, hh = q >> 11;
            const float4 v = *(float4*)&stage[(4 * r + n) * P + hh * 64 + d4 * 4];
            const float h0 = bfhi(v.x), h1 = bfhi(v.y), h2 = bfhi(v.z), h3 = bfhi(v.w);
            uint2 hp = { bfpack(h0, h1), bfpack(h2, h3) };
            uint2 lp = { bfpack(v.x - h0, v.y - h1), bfpack(v.z - h2, v.w - h3) };
            const int hd = (bn0 >> 6) + hh;
            const size_t a = (((size_t)(n * NHEAD + hd) * LLEN) + (bm0 >> 2) + r) * DHEAD + d4 * 4;
            *(uint2*)(dh + a) = hp;
            *(uint2*)(dl + a) = lp;
        }
    } else {
        #pragma unroll
        for (int i = 0; i < 16; i++) {
            const int q = t + 256 * i;
            const int s4 = q & 7, d = (q >> 3) & 63, n = (q >> 9) & 3, hh = q >> 11;
            float4 v;
            v.x = stage[(4 * (s4 * 4 + 0) + n) * P + hh * 64 + d];
            v.y = stage[(4 * (s4 * 4 + 1) + n) * P + hh * 64 + d];
            v.z = stage[(4 * (s4 * 4 + 2) + n) * P + hh * 64 + d];
            v.w = stage[(4 * (s4 * 4 + 3) + n) * P + hh * 64 + d];
            const float h0 = bfhi(v.x), h1 = bfhi(v.y), h2 = bfhi(v.z), h3 = bfhi(v.w);
            uint2 hp = { bfpack(h0, h1), bfpack(h2, h3) };
            uint2 lp = { bfpack(v.x - h0, v.y - h1), bfpack(v.z - h2, v.w - h3) };
            const int hd = (bn0 >> 6) + hh;
            const size_t a = ((size_t)(n * NHEAD + hd) * DHEAD + d) * SLEN + (bm0 >> 2) + s4 * 4;
            *(uint2*)(g_Vhi + a) = hp;
            *(uint2*)(g_Vlo + a) = lp;
        }
    }
}

// ---------------------------------------------------------------------------
// Out projection: out = ctx[8192,1024] @ Wo^T + bo
// ---------------------------------------------------------------------------
__global__ void __launch_bounds__(256, 2)
out_gemm(const float* __restrict__ Bin, const float* __restrict__ bias,
         float* __restrict__ Cout)
{
    constexpr int KK = 1024, NC = KK / 32;
    constexpr uint32_t AHI = 0, ALO = 8192, BHI = 16384, BLO = 24576;

    extern __shared__ char smp[];
    const int t = threadIdx.x, lane = t & 31, wid = t >> 5;
    const int wm = (wid >> 2) * 64;
    const int wn = (wid & 3) * 32;
    const int bm0 = blockIdx.y * 128, bn0 = blockIdx.x * 128;

    const float* Asrc = g_ctx + (size_t)bm0 * KK;
    const float* Bsrc = Bin + (size_t)bn0 * KK;

    float acc[4][4][4];
    #pragma unroll
    for (int m = 0; m < 4; m++)
        #pragma unroll
        for (int n = 0; n < 4; n++)
            #pragma unroll
            for (int v = 0; v < 4; v++) acc[m][n][v] = 0.0f;

    const int arow  = wm + ((lane >> 3) & 1) * 8 + (lane & 7);
    const int acsel = lane >> 4;
    const int brow  = wn + (lane >> 4) * 8 + (lane & 7);
    const int bcsel = (lane >> 3) & 1;
    const uint32_t smb = smem_u32(smp);

    for (int c = 0; c < NC; c++) {
        load_chunk<128, KK>(smp, AHI, ALO, Asrc + c * 32, t);
        load_chunk<128, KK>(smp, BHI, BLO, Bsrc + c * 32, t);
        __syncthreads();
        #pragma unroll
        for (int kk = 0; kk < 2; kk++) {
            uint32_t Bh[4][2], Bl[4][2];
            #pragma unroll
            for (int p = 0; p < 2; p++) {
                const int r = brow + p * 16;
                const uint32_t ba = smb + BHI + r * 64 +
                    ((uint32_t)((kk * 2 + bcsel) ^ ((r >> 1) & 3)) << 4);
                ldsm4(Bh[2*p][0], Bh[2*p][1], Bh[2*p+1][0], Bh[2*p+1][1], ba);
                ldsm4(Bl[2*p][0], Bl[2*p][1], Bl[2*p+1][0], Bl[2*p+1][1], ba + (BLO - BHI));
            }
            #pragma unroll
            for (int mt = 0; mt < 4; mt++) {
                const int r = arow + mt * 16;
                const uint32_t aa = smb + AHI + r * 64 +
                    ((uint32_t)((kk * 2 + acsel) ^ ((r >> 1) & 3)) << 4);
                uint32_t Ah[4], Al[4];
                ldsm4(Ah[0], Ah[1], Ah[2], Ah[3], aa);
                ldsm4(Al[0], Al[1], Al[2], Al[3], aa + (ALO - AHI));
                #pragma unroll
                for (int nt = 0; nt < 4; nt++) {
                    mma16816(acc[mt][nt], Ah, Bh[nt]);
                    mma16816(acc[mt][nt], Al, Bh[nt]);
                    mma16816(acc[mt][nt], Ah, Bl[nt]);
                }
            }
        }
        __syncthreads();
    }

    #pragma unroll
    for (int mt = 0; mt < 4; mt++) {
        const int r = bm0 + wm + mt * 16 + (lane >> 2);
        #pragma unroll
        for (int nt = 0; nt < 4; nt++) {
            const int cc = bn0 + wn + nt * 8 + (lane & 3) * 2;
            const float2 bb = *(const float2*)&bias[cc];
            float* d0 = Cout + (size_t)r * EDIM + cc;
            float2 v0 = { acc[mt][nt][0] + bb.x, acc[mt][nt][1] + bb.y };
            float2 v1 = { acc[mt][nt][2] + bb.x, acc[mt][nt][3] + bb.y };
            *(float2*)d0 = v0;
            *(float2*)(d0 + 8 * EDIM) = v1;
        }
    }
}

// ---------------------------------------------------------------------------
// Scores GEMM: per z=(n,h): S = Qz[2048,64] @ Kz[2048,64]^T (Q pre-scaled).
// bf16 hi/lo logits out via smem-staged coalesced STG.128.
// Input smem: 128B rows, swizzle kc ^ (r&7). Stage pitch 272B (conflict-free).
// ---------------------------------------------------------------------------
__global__ void __launch_bounds__(256, 2)
qk_gemm()
{
    constexpr uint32_t AHI = 0, ALO = 16384, BHI = 32768, BLO = 49152;
    constexpr uint32_t SP = 272;            // stage pitch bytes
    constexpr uint32_t SLO = 34816;         // 128 * 272
    extern __shared__ char smp[];
    const int t = threadIdx.x, lane = t & 31, wid = t >> 5;
    const int wm = (wid >> 2) * 64, wn = (wid & 3) * 32;
    const int bm0 = blockIdx.y * 128, bn0 = blockIdx.x * 128, z = blockIdx.z;
    const uint32_t smb = smem_u32(smp);

    const __nv_bfloat16* Ahg = g_Qhi + (size_t)z * LLEN * DHEAD + (size_t)bm0 * 64;
    const __nv_bfloat16* Alg = g_Qlo + (size_t)z * LLEN * DHEAD + (size_t)bm0 * 64;
    const __nv_bfloat16* Bhg = g_Khi + (size_t)z * SLEN * DHEAD + (size_t)bn0 * 64;
    const __nv_bfloat16* Blg = g_Klo + (size_t)z * SLEN * DHEAD + (size_t)bn0 * 64;

    #pragma unroll
    for (int i = 0; i < 4; i++) {
        const int idx = t + 256 * i;
        const int r = idx >> 3, kc = idx & 7;
        const uint32_t so = r * 128 + ((uint32_t)(kc ^ (r & 7)) << 4);
        const size_t go = (size_t)r * 64 + kc * 8;
        CPA16(smb + AHI + so, Ahg + go);
        CPA16(smb + ALO + so, Alg + go);
        CPA16(smb + BHI + so, Bhg + go);
        CPA16(smb + BLO + so, Blg + go);
    }
    CPCOMMIT(); CPWAIT0();
    __syncthreads();

    float acc[4][4][4];
    #pragma unroll
    for (int m = 0; m < 4; m++)
        #pragma unroll
        for (int n = 0; n < 4; n++)
            #pragma unroll
            for (int v = 0; v < 4; v++) acc[m][n][v] = 0.0f;

    const int arow  = wm + ((lane >> 3) & 1) * 8 + (lane & 7);
    const int acsel = lane >> 4;
    const int brow  = wn + (lane >> 4) * 8 + (lane & 7);
    const int bcsel = (lane >> 3) & 1;

    #pragma unroll
    for (int kk = 0; kk < 4; kk++) {
        uint32_t Bh[4][2], Bl[4][2];
        #pragma unroll
        for (int p = 0; p < 2; p++) {
            const int r = brow + p * 16, kc = kk * 2 + bcsel;
            const uint32_t ba = smb + BHI + r * 128 + ((uint32_t)(kc ^ (r & 7)) << 4);
            ldsm4(Bh[2*p][0], Bh[2*p][1], Bh[2*p+1][0], Bh[2*p+1][1], ba);
            ldsm4(Bl[2*p][0], Bl[2*p][1], Bl[2*p+1][0], Bl[2*p+1][1], ba + (BLO - BHI));
        }
        #pragma unroll
        for (int mt = 0; mt < 4; mt++) {
            const int r = arow + mt * 16, kc = kk * 2 + acsel;
            const uint32_t aa = smb + AHI + r * 128 + ((uint32_t)(kc ^ (r & 7)) << 4);
            uint32_t Ah[4], Al[4];
            ldsm4(Ah[0], Ah[1], Ah[2], Ah[3], aa);
            ldsm4(Al[0], Al[1], Al[2], Al[3], aa + (ALO - AHI));
            #pragma unroll
            for (int nt = 0; nt < 4; nt++) {
                mma16816(acc[mt][nt], Ah, Bh[nt]);
                mma16816(acc[mt][nt], Al, Bh[nt]);
                mma16816(acc[mt][nt], Ah, Bl[nt]);
            }
        }
    }

    // ---- stage bf16 hi/lo in smem, then coalesced copy-out ----
    __syncthreads();
    #pragma unroll
    for (int mt = 0; mt < 4; mt++) {
        const int rl = wm + mt * 16 + (lane >> 2);
        #pragma unroll
        for (int nt = 0; nt < 4; nt++) {
            const int cl = wn + nt * 8 + (lane & 3) * 2;
            const float v0x = acc[mt][nt][0], v0y = acc[mt][nt][1];
            const float v1x = acc[mt][nt][2], v1y = acc[mt][nt][3];
            const float h0x = bfhi(v0x), h0y = bfhi(v0y);
            const float h1x = bfhi(v1x), h1y = bfhi(v1y);
            const uint32_t o0 = rl * SP + cl * 2;
            const uint32_t o1 = (rl + 8) * SP + cl * 2;
            *(uint32_t*)(smp + o0)       = bfpack(h0x, h0y);
            *(uint32_t*)(smp + o0 + SLO) = bfpack(v0x - h0x, v0y - h0y);
            *(uint32_t*)(smp + o1)       = bfpack(h1x, h1y);
            *(uint32_t*)(smp + o1 + SLO) = bfpack(v1x - h1x, v1y - h1y);
        }
    }
    __syncthreads();
    const size_t zoff = (size_t)z * LLEN * SLEN;
    #pragma unroll
    for (int i = 0; i < 8; i++) {
        const int idx = t + 256 * i;
        const int row = idx >> 4, c = idx & 15;
        const uint32_t so = row * SP + c * 16;
        const size_t go = zoff + (size_t)(bm0 + row) * SLEN + bn0 + c * 8;
        *(uint4*)(g_Shi + go) = *(const uint4*)(smp + so);
        *(uint4*)(g_Slo + go) = *(const uint4*)(smp + so + SLO);
    }
}

// ---------------------------------------------------------------------------
// P @ V GEMM: per z: ctx = P[2048,2048] @ Vt[64,2048]^T -> g_ctx scatter.
// Probs hi/lo read from g_Shi/g_Slo (in-place after softmax).
// 2-stage cp.async pipeline. smem: 64B rows, swizzle kc ^ ((r>>1)&3).
// ---------------------------------------------------------------------------
__global__ void __launch_bounds__(256, 2)
pv_gemm()
{
    constexpr int NC = 64;
    constexpr uint32_t STG = 24576, AHI = 0, ALO = 8192, BHI = 16384, BLO = 20480;
    extern __shared__ char smp[];
    const int t = threadIdx.x, lane = t & 31, wid = t >> 5;
    const int wm = (wid >> 2) * 64, wn = (wid & 3) * 16;
    const int bm0 = blockIdx.y * 128, z = blockIdx.z;
    const uint32_t smb = smem_u32(smp);

    const __nv_bfloat16* Ahg = g_Shi + (size_t)z * LLEN * SLEN + (size_t)bm0 * 2048;
    const __nv_bfloat16* Alg = g_Slo + (size_t)z * LLEN * SLEN + (size_t)bm0 * 2048;
    const __nv_bfloat16* Bhg = g_Vhi + (size_t)z * DHEAD * SLEN;
    const __nv_bfloat16* Blg = g_Vlo + (size_t)z * DHEAD * SLEN;

    auto issue = [&](int c) {
        const uint32_t sb = (uint32_t)(c & 1) * STG;
        #pragma unroll
        for (int i = 0; i < 2; i++) {
            const int idx = t + 256 * i;
            const int r = idx >> 2, kc = idx & 3;
            const uint32_t so = r * 64 + ((uint32_t)(kc ^ ((r >> 1) & 3)) << 4);
            const size_t go = (size_t)r * 2048 + c * 32 + kc * 8;
            CPA16(smb + sb + AHI + so, Ahg + go);
            CPA16(smb + sb + ALO + so, Alg + go);
        }
        {
            const int r = t >> 2, kc = t & 3;   // 64 rows x 4 chunks
            const uint32_t so = r * 64 + ((uint32_t)(kc ^ ((r >> 1) & 3)) << 4);
            const size_t go = (size_t)r * 2048 + c * 32 + kc * 8;
            CPA16(smb + sb + BHI + so, Bhg + go);
            CPA16(smb + sb + BLO + so, Blg + go);
        }
        CPCOMMIT();
    };

    issue(0); issue(1);

    float acc[4][2][4];
    #pragma unroll
    for (int m = 0; m < 4; m++)
        #pragma unroll
        for (int n = 0; n < 2; n++)
            #pragma unroll
            for (int v = 0; v < 4; v++) acc[m][n][v] = 0.0f;

    const int arow  = wm + ((lane >> 3) & 1) * 8 + (lane & 7);
    const int acsel = lane >> 4;
    const int brow  = wn + (lane >> 4) * 8 + (lane & 7);
    const int bcsel = (lane >> 3) & 1;

    for (int c = 0; c < NC; c++) {
        if (c + 1 < NC) { CPWAIT1(); } else { CPWAIT0(); }
        __syncthreads();
        const uint32_t sb = (uint32_t)(c & 1) * STG;
        #pragma unroll
        for (int kk = 0; kk < 2; kk++) {
            uint32_t Bh[2][2], Bl[2][2];
            {
                const int r = brow, kc = kk * 2 + bcsel;
                const uint32_t ba = smb + sb + BHI + r * 64 +
                    ((uint32_t)(kc ^ ((r >> 1) & 3)) << 4);
                ldsm4(Bh[0][0], Bh[0][1], Bh[1][0], Bh[1][1], ba);
                ldsm4(Bl[0][0], Bl[0][1], Bl[1][0], Bl[1][1], ba + (BLO - BHI));
            }
            #pragma unroll
            for (int mt = 0; mt < 4; mt++) {
                const int r = arow + mt * 16, kc = kk * 2 + acsel;
                const uint32_t aa = smb + sb + AHI + r * 64 +
                    ((uint32_t)(kc ^ ((r >> 1) & 3)) << 4);
                uint32_t Ah[4], Al[4];
                ldsm4(Ah[0], Ah[1], Ah[2], Ah[3], aa);
                ldsm4(Al[0], Al[1], Al[2], Al[3], aa + (ALO - AHI));
                #pragma unroll
                for (int nt = 0; nt < 2; nt++) {
                    mma16816(acc[mt][nt], Ah, Bh[nt]);
                    mma16816(acc[mt][nt], Al, Bh[nt]);
                    mma16816(acc[mt][nt], Ah, Bl[nt]);
                }
            }
        }
        __syncthreads();
        if (c + 2 < NC) issue(c + 2);
    }

    const int n = z >> 4, h = z & 15;
    #pragma unroll
    for (int mt = 0; mt < 4; mt++) {
        const int r = bm0 + wm + mt * 16 + (lane >> 2);
        #pragma unroll
        for (int nt = 0; nt < 2; nt++) {
            const int cl = wn + nt * 8 + (lane & 3) * 2;
            float* d0 = g_ctx + (size_t)r * (NBAT * EDIM) + n * EDIM + h * DHEAD + cl;
            float2 v0 = { acc[mt][nt][0], acc[mt][nt][1] };
            float2 v1 = { acc[mt][nt][2], acc[mt][nt][3] };
            *(float2*)d0 = v0;
            *(float2*)(d0 + 8 * (NBAT * EDIM)) = v1;
        }
    }
}

// ---------------- fast exp on FMA pipe ----------------
__device__ __forceinline__ float fexp(float x)
{
    float y = x * 1.4426950408889634f;
    y = fmaxf(y, -120.0f);
    float r = rintf(y);
    float f = y - r;
    float p = 1.3333558146e-3f;
    p = fmaf(p, f, 9.6181291076e-3f);
    p = fmaf(p, f, 5.5504108665e-2f);
    p = fmaf(p, f, 2.4022650696e-1f);
    p = fmaf(p, f, 6.9314718056e-1f);
    p = fmaf(p, f, 1.0f);
    return p * __int_as_float(((int)r + 127) << 23);
}

// ---------------- fused softmax (16 heads) + head-mean; in-place probs ------
__global__ void __launch_bounds__(256)
softmax_mean_k(float* __restrict__ wavg)
{
    const int b = blockIdx.x;
    const int n = b >> 11, l = b & 2047;
    const int t = threadIdx.x;
    __shared__ float sh[8];
    float mean[8];
    #pragma unroll
    for (int i = 0; i < 8; i++) mean[i] = 0.0f;

    for (int h = 0; h < NHEAD; h++) {
        const size_t base = (((size_t)(n * NHEAD + h) * LLEN) + l) * SLEN + (size_t)t * 8;
        const uint4 ph = *(const uint4*)(g_Shi + base);
        const uint4 pl = *(const uint4*)(g_Slo + base);
        float x[8];
        {
            float2 a, c;
            a = bfunpack2(ph.x); c = bfunpack2(pl.x); x[0] = a.x + c.x; x[1] = a.y + c.y;
            a = bfunpack2(ph.y); c = bfunpack2(pl.y); x[2] = a.x + c.x; x[3] = a.y + c.y;
            a = bfunpack2(ph.z); c = bfunpack2(pl.z); x[4] = a.x + c.x; x[5] = a.y + c.y;
            a = bfunpack2(ph.w); c = bfunpack2(pl.w); x[6] = a.x + c.x; x[7] = a.y + c.y;
        }
        float m = x[0];
        #pragma unroll
        for (int i = 1; i < 8; i++) m = fmaxf(m, x[i]);
        #pragma unroll
        for (int o = 16; o > 0; o >>= 1) m = fmaxf(m, __shfl_xor_sync(0xffffffffu, m, o));
        if ((t & 31) == 0) sh[t >> 5] = m;
        __syncthreads();
        m = sh[t & 7];
        #pragma unroll
        for (int o = 4; o > 0; o >>= 1) m = fmaxf(m, __shfl_xor_sync(0xffffffffu, m, o));
        float s = 0.0f;
        #pragma unroll
        for (int i = 0; i < 8; i++) { x[i] = fexp(x[i] - m); s += x[i]; }
        #pragma unroll
        for (int o = 16; o > 0; o >>= 1) s += __shfl_xor_sync(0xffffffffu, s, o);
        __syncthreads();
        if ((t & 31) == 0) sh[t >> 5] = s;
        __syncthreads();
        s = sh[t & 7];
        #pragma unroll
        for (int o = 4; o > 0; o >>= 1) s += __shfl_xor_sync(0xffffffffu, s, o);
        const float inv = 1.0f / s;
        uint4 oh, ol;
        float hx, hy;
        #pragma unroll
        for (int i = 0; i < 8; i++) { x[i] *= inv; mean[i] += x[i]; }
        hx = bfhi(x[0]); hy = bfhi(x[1]);
        oh.x = bfpack(hx, hy); ol.x = bfpack(x[0] - hx, x[1] - hy);
        hx = bfhi(x[2]); hy = bfhi(x[3]);
        oh.y = bfpack(hx, hy); ol.y = bfpack(x[2] - hx, x[3] - hy);
        hx = bfhi(x[4]); hy = bfhi(x[5]);
        oh.z = bfpack(hx, hy); ol.z = bfpack(x[4] - hx, x[5] - hy);
        hx = bfhi(x[6]); hy = bfhi(x[7]);
        oh.w = bfpack(hx, hy); ol.w = bfpack(x[6] - hx, x[7] - hy);
        *(uint4*)(g_Shi + base) = oh;
        *(uint4*)(g_Slo + base) = ol;
        __syncthreads();
    }
    float4* w = (float4*)(wavg + (size_t)b * SLEN + (size_t)t * 8);
    float4 w0 = { mean[0] * 0.0625f, mean[1] * 0.0625f, mean[2] * 0.0625f, mean[3] * 0.0625f };
    float4 w1 = { mean[4] * 0.0625f, mean[5] * 0.0625f, mean[6] * 0.0625f, mean[7] * 0.0625f };
    w[0] = w0;
    w[1] = w1;
}

// ---------------- launcher ----------------
extern "C" void kernel_launch(void* const* d_in, const int* in_sizes, int n_in,
                              void* d_out, int out_size)
{
    const float* query = (const float*)d_in[0];
    const float* key   = (const float*)d_in[1];
    const float* value = (const float*)d_in[2];
    const float* Wq = (const float*)d_in[3];  const float* bq = (const float*)d_in[4];
    const float* Wk = (const float*)d_in[5];  const float* bk = (const float*)d_in[6];
    const float* Wv = (const float*)d_in[7];  const float* bv = (const float*)d_in[8];
    const float* Wo = (const float*)d_in[9];  const float* bo = (const float*)d_in[10];
    float* out  = (float*)d_out;
    float* wavg = out + (size_t)LLEN * NBAT * EDIM;

    const int SQKV = 69632;   // mainloop 32KB; epilogue stage 128*132*4 = 67584
    const int SO   = 32768;
    const int SQK  = 69632;   // tiles 64KB; stage 2*34816 = 69632 (overlap)
    const int SPV  = 49152;
    cudaFuncSetAttribute(qkv_gemm, cudaFuncAttributeMaxDynamicSharedMemorySize, SQKV);
    cudaFuncSetAttribute(out_gemm, cudaFuncAttributeMaxDynamicSharedMemorySize, SO);
    cudaFuncSetAttribute(qk_gemm,  cudaFuncAttributeMaxDynamicSharedMemorySize, SQK);
    cudaFuncSetAttribute(pv_gemm,  cudaFuncAttributeMaxDynamicSharedMemorySize, SPV);

    dim3 thr(256);
    qkv_gemm<<<dim3(8, 64, 3), thr, SQKV>>>(query, key, value, Wq, Wk, Wv, bq, bk, bv);
    qk_gemm<<<dim3(16, 16, 64), thr, SQK>>>();
    softmax_mean_k<<<NBAT * LLEN, thr>>>(wavg);
    pv_gemm<<<dim3(1, 16, 64), thr, SPV>>>();
    out_gemm<<<dim3(8, 64, 1), thr, SO>>>(Wo, bo, out);
}

// round 13
// speedup vs baseline: 2.8507x; 1.0479x over previous
#include <cuda_runtime.h>
#include <cuda_bf16.h>
#include <cstdint>

#define LLEN 2048
#define SLEN 2048
#define NBAT 4
#define EDIM 1024
#define NHEAD 16
#define DHEAD 64

// ---------------- device scratch (allocation-free rule; < 2GB total) -------
// All GEMM operands pre-split as bf16 hi/lo pairs (x = hi + lo, fp32-grade).
__device__ __nv_bfloat16 g_Xhi[(size_t)3*8192*1024];           // inputs q,k,v
__device__ __nv_bfloat16 g_Xlo[(size_t)3*8192*1024];
__device__ __nv_bfloat16 g_Whi[(size_t)4*1024*1024];           // Wq,Wk,Wv,Wo
__device__ __nv_bfloat16 g_Wlo[(size_t)4*1024*1024];
__device__ __nv_bfloat16 g_Qhi[(size_t)NBAT*NHEAD*LLEN*DHEAD]; // [n,h,l,d] (pre-scaled 0.125)
__device__ __nv_bfloat16 g_Qlo[(size_t)NBAT*NHEAD*LLEN*DHEAD];
__device__ __nv_bfloat16 g_Khi[(size_t)NBAT*NHEAD*SLEN*DHEAD]; // [n,h,s,d]
__device__ __nv_bfloat16 g_Klo[(size_t)NBAT*NHEAD*SLEN*DHEAD];
__device__ __nv_bfloat16 g_Vhi[(size_t)NBAT*NHEAD*DHEAD*SLEN]; // [n,h,d,s]
__device__ __nv_bfloat16 g_Vlo[(size_t)NBAT*NHEAD*DHEAD*SLEN];
// scores hi/lo -> overwritten in place by probs hi/lo after softmax
__device__ __nv_bfloat16 g_Shi[(size_t)NBAT*NHEAD*LLEN*SLEN];  // [n,h,l,s]
__device__ __nv_bfloat16 g_Slo[(size_t)NBAT*NHEAD*LLEN*SLEN];
__device__ __nv_bfloat16 g_Chi[(size_t)8192*1024];             // ctx [l,n,e]
__device__ __nv_bfloat16 g_Clo[(size_t)8192*1024];

// ---------------- helpers ----------------
__device__ __forceinline__ uint32_t smem_u32(const void* p) {
    uint32_t a;
    asm("{ .reg .u64 t; cvta.to.shared.u64 t, %1; cvt.u32.u64 %0, t; }" : "=r"(a) : "l"(p));
    return a;
}
__device__ __forceinline__ uint32_t bfpack(float a, float b) {
    uint32_t r;
    asm("cvt.rn.bf16x2.f32 %0, %1, %2;" : "=r"(r) : "f"(b), "f"(a));
    return r;
}
__device__ __forceinline__ float2 bfunpack2(uint32_t p) {
    float2 r;
    r.x = __uint_as_float(p << 16);
    r.y = __uint_as_float(p & 0xffff0000u);
    return r;
}
__device__ __forceinline__ float bfhi(float x) {
    return __bfloat162float(__float2bfloat16(x));
}
__device__ __forceinline__ void ldsm4(uint32_t& r0, uint32_t& r1, uint32_t& r2, uint32_t& r3,
                                      uint32_t addr) {
    asm volatile("ldmatrix.sync.aligned.m8n8.x4.shared.b16 {%0,%1,%2,%3}, [%4];"
                 : "=r"(r0), "=r"(r1), "=r"(r2), "=r"(r3) : "r"(addr));
}
__device__ __forceinline__ void mma16816(float* c, const uint32_t* a, const uint32_t* b) {
    asm volatile("mma.sync.aligned.m16n8k16.row.col.f32.bf16.bf16.f32 "
                 "{%0,%1,%2,%3}, {%4,%5,%6,%7}, {%8,%9}, {%0,%1,%2,%3};"
                 : "+f"(c[0]), "+f"(c[1]), "+f"(c[2]), "+f"(c[3])
                 : "r"(a[0]), "r"(a[1]), "r"(a[2]), "r"(a[3]), "r"(b[0]), "r"(b[1]));
}
#define CPA16(sm, gp) asm volatile("cp.async.cg.shared.global [%0], [%1], 16;" :: "r"(sm), "l"(gp))
#define CPCOMMIT()    asm volatile("cp.async.commit_group;" ::: "memory")
#define CPWAIT0()     asm volatile("cp.async.wait_group 0;" ::: "memory")
#define CPWAIT1()     asm volatile("cp.async.wait_group 1;" ::: "memory")
#define CPWAIT2()     asm volatile("cp.async.wait_group 2;" ::: "memory")

// ---------------------------------------------------------------------------
// Pre-split: fp32 inputs/weights -> bf16 hi/lo pairs (one elementwise pass).
// z: 0..2 inputs (8388608 elems), 3..6 weights (1048576 elems).
// ---------------------------------------------------------------------------
__global__ void __launch_bounds__(256)
split_k(const float* __restrict__ q, const float* __restrict__ k,
        const float* __restrict__ v,
        const float* __restrict__ wq, const float* __restrict__ wk,
        const float* __restrict__ wv, const float* __restrict__ wo)
{
    const int z = blockIdx.z;
    const float* src; __nv_bfloat16 *dh, *dl; size_t n;
    if (z < 3) {
        src = (z == 0) ? q : ((z == 1) ? k : v);
        dh = g_Xhi + (size_t)z * 8388608; dl = g_Xlo + (size_t)z * 8388608;
        n = 8388608;
    } else {
        const int w = z - 3;
        src = (w == 0) ? wq : ((w == 1) ? wk : ((w == 2) ? wv : wo));
        dh = g_Whi + (size_t)w * 1048576; dl = g_Wlo + (size_t)w * 1048576;
        n = 1048576;
    }
    const size_t i = ((size_t)blockIdx.x * 256 + threadIdx.x) * 8;
    if (i >= n) return;
    const float4 v0 = *(const float4*)(src + i);
    const float4 v1 = *(const float4*)(src + i + 4);
    float f[8] = { v0.x, v0.y, v0.z, v0.w, v1.x, v1.y, v1.z, v1.w };
    float h[8];
    #pragma unroll
    for (int j = 0; j < 8; j++) h[j] = bfhi(f[j]);
    uint4 h4, l4;
    h4.x = bfpack(h[0], h[1]); h4.y = bfpack(h[2], h[3]);
    h4.z = bfpack(h[4], h[5]); h4.w = bfpack(h[6], h[7]);
    l4.x = bfpack(f[0]-h[0], f[1]-h[1]); l4.y = bfpack(f[2]-h[2], f[3]-h[3]);
    l4.z = bfpack(f[4]-h[4], f[5]-h[5]); l4.w = bfpack(f[6]-h[6], f[7]-h[7]);
    *(uint4*)(dh + i) = h4;
    *(uint4*)(dl + i) = l4;
}

// ---------------------------------------------------------------------------
// Fused Q/K/V projection GEMM (z selects 0:Q 1:K 2:V). Pure-copy 3-stage
// cp.async loaders from pre-split operands. Q scaled by 0.125 in epilogue.
// smem: 64B rows, swizzle kc ^ ((r>>1)&3). Stage = 32 KB.
// ---------------------------------------------------------------------------
__global__ void __launch_bounds__(256, 2)
qkv_gemm(const float* __restrict__ bq, const float* __restrict__ bk,
         const float* __restrict__ bv)
{
    constexpr int NC = 32;
    constexpr uint32_t STG = 32768, AHI = 0, ALO = 8192, BHI = 16384, BLO = 24576;

    extern __shared__ char smp[];
    const int t = threadIdx.x, lane = t & 31, wid = t >> 5;
    const int wm = (wid >> 2) * 64, wn = (wid & 3) * 32;
    const int bm0 = blockIdx.y * 128, bn0 = blockIdx.x * 128, z = blockIdx.z;
    const uint32_t smb = smem_u32(smp);

    const __nv_bfloat16* Ahg = g_Xhi + (size_t)z * 8388608 + (size_t)bm0 * 1024;
    const __nv_bfloat16* Alg = g_Xlo + (size_t)z * 8388608 + (size_t)bm0 * 1024;
    const __nv_bfloat16* Bhg = g_Whi + (size_t)z * 1048576 + (size_t)bn0 * 1024;
    const __nv_bfloat16* Blg = g_Wlo + (size_t)z * 1048576 + (size_t)bn0 * 1024;
    const float* bias = (z == 0) ? bq : ((z == 1) ? bk : bv);
    const float  sc   = (z == 0) ? 0.125f : 1.0f;

    auto issue = [&](int c) {
        const uint32_t sb = (uint32_t)(c % 3) * STG;
        #pragma unroll
        for (int i = 0; i < 2; i++) {
            const int idx = t + 256 * i;
            const int r = idx >> 2, kc = idx & 3;
            const uint32_t so = r * 64 + ((uint32_t)(kc ^ ((r >> 1) & 3)) << 4);
            const size_t go = (size_t)r * 1024 + c * 32 + kc * 8;
            CPA16(smb + sb + AHI + so, Ahg + go);
            CPA16(smb + sb + ALO + so, Alg + go);
            CPA16(smb + sb + BHI + so, Bhg + go);
            CPA16(smb + sb + BLO + so, Blg + go);
        }
        CPCOMMIT();
    };
    issue(0); issue(1); issue(2);

    float acc[4][4][4];
    #pragma unroll
    for (int m = 0; m < 4; m++)
        #pragma unroll
        for (int n = 0; n < 4; n++)
            #pragma unroll
            for (int v = 0; v < 4; v++) acc[m][n][v] = 0.0f;

    const int arow  = wm + ((lane >> 3) & 1) * 8 + (lane & 7);
    const int acsel = lane >> 4;
    const int brow  = wn + (lane >> 4) * 8 + (lane & 7);
    const int bcsel = (lane >> 3) & 1;

    for (int c = 0; c < NC; c++) {
        if (c + 2 < NC) { CPWAIT2(); } else if (c + 1 < NC) { CPWAIT1(); } else { CPWAIT0(); }
        __syncthreads();
        const uint32_t sb = (uint32_t)(c % 3) * STG;
        #pragma unroll
        for (int kk = 0; kk < 2; kk++) {
            uint32_t Bh[4][2], Bl[4][2];
            #pragma unroll
            for (int p = 0; p < 2; p++) {
                const int r = brow + p * 16;
                const uint32_t ba = smb + sb + BHI + r * 64 +
                    ((uint32_t)((kk * 2 + bcsel) ^ ((r >> 1) & 3)) << 4);
                ldsm4(Bh[2*p][0], Bh[2*p][1], Bh[2*p+1][0], Bh[2*p+1][1], ba);
                ldsm4(Bl[2*p][0], Bl[2*p][1], Bl[2*p+1][0], Bl[2*p+1][1], ba + (BLO - BHI));
            }
            #pragma unroll
            for (int mt = 0; mt < 4; mt++) {
                const int r = arow + mt * 16;
                const uint32_t aa = smb + sb + AHI + r * 64 +
                    ((uint32_t)((kk * 2 + acsel) ^ ((r >> 1) & 3)) << 4);
                uint32_t Ah[4], Al[4];
                ldsm4(Ah[0], Ah[1], Ah[2], Ah[3], aa);
                ldsm4(Al[0], Al[1], Al[2], Al[3], aa + (ALO - AHI));
                #pragma unroll
                for (int nt = 0; nt < 4; nt++) {
                    mma16816(acc[mt][nt], Ah, Bh[nt]);
                    mma16816(acc[mt][nt], Al, Bh[nt]);
                    mma16816(acc[mt][nt], Ah, Bl[nt]);
                }
            }
        }
        __syncthreads();
        if (c + 3 < NC) issue(c + 3);
    }

    // stage fp32 (with bias, scale) then scatter bf16 hi/lo into head layouts
    constexpr int P = 132;
    float* stage = (float*)smp;
    #pragma unroll
    for (int mt = 0; mt < 4; mt++) {
        const int rl = wm + mt * 16 + (lane >> 2);
        #pragma unroll
        for (int nt = 0; nt < 4; nt++) {
            const int cl = wn + nt * 8 + (lane & 3) * 2;
            const float2 bb = *(const float2*)&bias[bn0 + cl];
            float2 v0 = { (acc[mt][nt][0] + bb.x) * sc, (acc[mt][nt][1] + bb.y) * sc };
            float2 v1 = { (acc[mt][nt][2] + bb.x) * sc, (acc[mt][nt][3] + bb.y) * sc };
            *(float2*)&stage[rl * P + cl] = v0;
            *(float2*)&stage[(rl + 8) * P + cl] = v1;
        }
    }
    __syncthreads();
    if (z <= 1) {
        __nv_bfloat16* dh = (z == 0) ? g_Qhi : g_Khi;
        __nv_bfloat16* dl = (z == 0) ? g_Qlo : g_Klo;
        #pragma unroll
        for (int i = 0; i < 16; i++) {
            const int q = t + 256 * i;
            const int d4 = q & 15, r = (q >> 4) & 31, n = (q >> 9) & 3, hh = q >> 11;
            const float4 v = *(float4*)&stage[(4 * r + n) * P + hh * 64 + d4 * 4];
            const float h0 = bfhi(v.x), h1 = bfhi(v.y), h2 = bfhi(v.z), h3 = bfhi(v.w);
            uint2 hp = { bfpack(h0, h1), bfpack(h2, h3) };
            uint2 lp = { bfpack(v.x - h0, v.y - h1), bfpack(v.z - h2, v.w - h3) };
            const int hd = (bn0 >> 6) + hh;
            const size_t a = (((size_t)(n * NHEAD + hd) * LLEN) + (bm0 >> 2) + r) * DHEAD + d4 * 4;
            *(uint2*)(dh + a) = hp;
            *(uint2*)(dl + a) = lp;
        }
    } else {
        #pragma unroll
        for (int i = 0; i < 16; i++) {
            const int q = t + 256 * i;
            const int s4 = q & 7, d = (q >> 3) & 63, n = (q >> 9) & 3, hh = q >> 11;
            float4 v;
            v.x = stage[(4 * (s4 * 4 + 0) + n) * P + hh * 64 + d];
            v.y = stage[(4 * (s4 * 4 + 1) + n) * P + hh * 64 + d];
            v.z = stage[(4 * (s4 * 4 + 2) + n) * P + hh * 64 + d];
            v.w = stage[(4 * (s4 * 4 + 3) + n) * P + hh * 64 + d];
            const float h0 = bfhi(v.x), h1 = bfhi(v.y), h2 = bfhi(v.z), h3 = bfhi(v.w);
            uint2 hp = { bfpack(h0, h1), bfpack(h2, h3) };
            uint2 lp = { bfpack(v.x - h0, v.y - h1), bfpack(v.z - h2, v.w - h3) };
            const int hd = (bn0 >> 6) + hh;
            const size_t a = ((size_t)(n * NHEAD + hd) * DHEAD + d) * SLEN + (bm0 >> 2) + s4 * 4;
            *(uint2*)(g_Vhi + a) = hp;
            *(uint2*)(g_Vlo + a) = lp;
        }
    }
}

// ---------------------------------------------------------------------------
// Out projection: out = ctx @ Wo^T + bo. Pure-copy 3-stage cp.async loaders
// from pre-split g_Chi/g_Clo and weight slice 3.
// ---------------------------------------------------------------------------
__global__ void __launch_bounds__(256, 2)
out_gemm(const float* __restrict__ bias, float* __restrict__ Cout)
{
    constexpr int NC = 32;
    constexpr uint32_t STG = 32768, AHI = 0, ALO = 8192, BHI = 16384, BLO = 24576;

    extern __shared__ char smp[];
    const int t = threadIdx.x, lane = t & 31, wid = t >> 5;
    const int wm = (wid >> 2) * 64, wn = (wid & 3) * 32;
    const int bm0 = blockIdx.y * 128, bn0 = blockIdx.x * 128;
    const uint32_t smb = smem_u32(smp);

    const __nv_bfloat16* Ahg = g_Chi + (size_t)bm0 * 1024;
    const __nv_bfloat16* Alg = g_Clo + (size_t)bm0 * 1024;
    const __nv_bfloat16* Bhg = g_Whi + (size_t)3 * 1048576 + (size_t)bn0 * 1024;
    const __nv_bfloat16* Blg = g_Wlo + (size_t)3 * 1048576 + (size_t)bn0 * 1024;

    auto issue = [&](int c) {
        const uint32_t sb = (uint32_t)(c % 3) * STG;
        #pragma unroll
        for (int i = 0; i < 2; i++) {
            const int idx = t + 256 * i;
            const int r = idx >> 2, kc = idx & 3;
            const uint32_t so = r * 64 + ((uint32_t)(kc ^ ((r >> 1) & 3)) << 4);
            const size_t go = (size_t)r * 1024 + c * 32 + kc * 8;
            CPA16(smb + sb + AHI + so, Ahg + go);
            CPA16(smb + sb + ALO + so, Alg + go);
            CPA16(smb + sb + BHI + so, Bhg + go);
            CPA16(smb + sb + BLO + so, Blg + go);
        }
        CPCOMMIT();
    };
    issue(0); issue(1); issue(2);

    float acc[4][4][4];
    #pragma unroll
    for (int m = 0; m < 4; m++)
        #pragma unroll
        for (int n = 0; n < 4; n++)
            #pragma unroll
            for (int v = 0; v < 4; v++) acc[m][n][v] = 0.0f;

    const int arow  = wm + ((lane >> 3) & 1) * 8 + (lane & 7);
    const int acsel = lane >> 4;
    const int brow  = wn + (lane >> 4) * 8 + (lane & 7);
    const int bcsel = (lane >> 3) & 1;

    for (int c = 0; c < NC; c++) {
        if (c + 2 < NC) { CPWAIT2(); } else if (c + 1 < NC) { CPWAIT1(); } else { CPWAIT0(); }
        __syncthreads();
        const uint32_t sb = (uint32_t)(c % 3) * STG;
        #pragma unroll
        for (int kk = 0; kk < 2; kk++) {
            uint32_t Bh[4][2], Bl[4][2];
            #pragma unroll
            for (int p = 0; p < 2; p++) {
                const int r = brow + p * 16;
                const uint32_t ba = smb + sb + BHI + r * 64 +
                    ((uint32_t)((kk * 2 + bcsel) ^ ((r >> 1) & 3)) << 4);
                ldsm4(Bh[2*p][0], Bh[2*p][1], Bh[2*p+1][0], Bh[2*p+1][1], ba);
                ldsm4(Bl[2*p][0], Bl[2*p][1], Bl[2*p+1][0], Bl[2*p+1][1], ba + (BLO - BHI));
            }
            #pragma unroll
            for (int mt = 0; mt < 4; mt++) {
                const int r = arow + mt * 16;
                const uint32_t aa = smb + sb + AHI + r * 64 +
                    ((uint32_t)((kk * 2 + acsel) ^ ((r >> 1) & 3)) << 4);
                uint32_t Ah[4], Al[4];
                ldsm4(Ah[0], Ah[1], Ah[2], Ah[3], aa);
                ldsm4(Al[0], Al[1], Al[2], Al[3], aa + (ALO - AHI));
                #pragma unroll
                for (int nt = 0; nt < 4; nt++) {
                    mma16816(acc[mt][nt], Ah, Bh[nt]);
                    mma16816(acc[mt][nt], Al, Bh[nt]);
                    mma16816(acc[mt][nt], Ah, Bl[nt]);
                }
            }
        }
        __syncthreads();
        if (c + 3 < NC) issue(c + 3);
    }

    #pragma unroll
    for (int mt = 0; mt < 4; mt++) {
        const int r = bm0 + wm + mt * 16 + (lane >> 2);
        #pragma unroll
        for (int nt = 0; nt < 4; nt++) {
            const int cc = bn0 + wn + nt * 8 + (lane & 3) * 2;
            const float2 bb = *(const float2*)&bias[cc];
            float* d0 = Cout + (size_t)r * EDIM + cc;
            float2 v0 = { acc[mt][nt][0] + bb.x, acc[mt][nt][1] + bb.y };
            float2 v1 = { acc[mt][nt][2] + bb.x, acc[mt][nt][3] + bb.y };
            *(float2*)d0 = v0;
            *(float2*)(d0 + 8 * EDIM) = v1;
        }
    }
}

// ---------------------------------------------------------------------------
// Scores GEMM: per z=(n,h): S = Qz[2048,64] @ Kz[2048,64]^T (Q pre-scaled).
// bf16 hi/lo logits out via smem-staged coalesced STG.128.
// ---------------------------------------------------------------------------
__global__ void __launch_bounds__(256, 2)
qk_gemm()
{
    constexpr uint32_t AHI = 0, ALO = 16384, BHI = 32768, BLO = 49152;
    constexpr uint32_t SP = 272;            // stage pitch bytes
    constexpr uint32_t SLO = 34816;         // 128 * 272
    extern __shared__ char smp[];
    const int t = threadIdx.x, lane = t & 31, wid = t >> 5;
    const int wm = (wid >> 2) * 64, wn = (wid & 3) * 32;
    const int bm0 = blockIdx.y * 128, bn0 = blockIdx.x * 128, z = blockIdx.z;
    const uint32_t smb = smem_u32(smp);

    const __nv_bfloat16* Ahg = g_Qhi + (size_t)z * LLEN * DHEAD + (size_t)bm0 * 64;
    const __nv_bfloat16* Alg = g_Qlo + (size_t)z * LLEN * DHEAD + (size_t)bm0 * 64;
    const __nv_bfloat16* Bhg = g_Khi + (size_t)z * SLEN * DHEAD + (size_t)bn0 * 64;
    const __nv_bfloat16* Blg = g_Klo + (size_t)z * SLEN * DHEAD + (size_t)bn0 * 64;

    #pragma unroll
    for (int i = 0; i < 4; i++) {
        const int idx = t + 256 * i;
        const int r = idx >> 3, kc = idx & 7;
        const uint32_t so = r * 128 + ((uint32_t)(kc ^ (r & 7)) << 4);
        const size_t go = (size_t)r * 64 + kc * 8;
        CPA16(smb + AHI + so, Ahg + go);
        CPA16(smb + ALO + so, Alg + go);
        CPA16(smb + BHI + so, Bhg + go);
        CPA16(smb + BLO + so, Blg + go);
    }
    CPCOMMIT(); CPWAIT0();
    __syncthreads();

    float acc[4][4][4];
    #pragma unroll
    for (int m = 0; m < 4; m++)
        #pragma unroll
        for (int n = 0; n < 4; n++)
            #pragma unroll
            for (int v = 0; v < 4; v++) acc[m][n][v] = 0.0f;

    const int arow  = wm + ((lane >> 3) & 1) * 8 + (lane & 7);
    const int acsel = lane >> 4;
    const int brow  = wn + (lane >> 4) * 8 + (lane & 7);
    const int bcsel = (lane >> 3) & 1;

    #pragma unroll
    for (int kk = 0; kk < 4; kk++) {
        uint32_t Bh[4][2], Bl[4][2];
        #pragma unroll
        for (int p = 0; p < 2; p++) {
            const int r = brow + p * 16, kc = kk * 2 + bcsel;
            const uint32_t ba = smb + BHI + r * 128 + ((uint32_t)(kc ^ (r & 7)) << 4);
            ldsm4(Bh[2*p][0], Bh[2*p][1], Bh[2*p+1][0], Bh[2*p+1][1], ba);
            ldsm4(Bl[2*p][0], Bl[2*p][1], Bl[2*p+1][0], Bl[2*p+1][1], ba + (BLO - BHI));
        }
        #pragma unroll
        for (int mt = 0; mt < 4; mt++) {
            const int r = arow + mt * 16, kc = kk * 2 + acsel;
            const uint32_t aa = smb + AHI + r * 128 + ((uint32_t)(kc ^ (r & 7)) << 4);
            uint32_t Ah[4], Al[4];
            ldsm4(Ah[0], Ah[1], Ah[2], Ah[3], aa);
            ldsm4(Al[0], Al[1], Al[2], Al[3], aa + (ALO - AHI));
            #pragma unroll
            for (int nt = 0; nt < 4; nt++) {
                mma16816(acc[mt][nt], Ah, Bh[nt]);
                mma16816(acc[mt][nt], Al, Bh[nt]);
                mma16816(acc[mt][nt], Ah, Bl[nt]);
            }
        }
    }

    // ---- stage bf16 hi/lo in smem, then coalesced copy-out ----
    __syncthreads();
    #pragma unroll
    for (int mt = 0; mt < 4; mt++) {
        const int rl = wm + mt * 16 + (lane >> 2);
        #pragma unroll
        for (int nt = 0; nt < 4; nt++) {
            const int cl = wn + nt * 8 + (lane & 3) * 2;
            const float v0x = acc[mt][nt][0], v0y = acc[mt][nt][1];
            const float v1x = acc[mt][nt][2], v1y = acc[mt][nt][3];
            const float h0x = bfhi(v0x), h0y = bfhi(v0y);
            const float h1x = bfhi(v1x), h1y = bfhi(v1y);
            const uint32_t o0 = rl * SP + cl * 2;
            const uint32_t o1 = (rl + 8) * SP + cl * 2;
            *(uint32_t*)(smp + o0)       = bfpack(h0x, h0y);
            *(uint32_t*)(smp + o0 + SLO) = bfpack(v0x - h0x, v0y - h0y);
            *(uint32_t*)(smp + o1)       = bfpack(h1x, h1y);
            *(uint32_t*)(smp + o1 + SLO) = bfpack(v1x - h1x, v1y - h1y);
        }
    }
    __syncthreads();
    const size_t zoff = (size_t)z * LLEN * SLEN;
    #pragma unroll
    for (int i = 0; i < 8; i++) {
        const int idx = t + 256 * i;
        const int row = idx >> 4, c = idx & 15;
        const uint32_t so = row * SP + c * 16;
        const size_t go = zoff + (size_t)(bm0 + row) * SLEN + bn0 + c * 8;
        *(uint4*)(g_Shi + go) = *(const uint4*)(smp + so);
        *(uint4*)(g_Slo + go) = *(const uint4*)(smp + so + SLO);
    }
}

// ---------------------------------------------------------------------------
// P @ V GEMM: per z: ctx = P[2048,2048] @ Vt[64,2048]^T -> g_Chi/g_Clo.
// 3-stage cp.async pipeline. smem: 64B rows, swizzle kc ^ ((r>>1)&3).
// ---------------------------------------------------------------------------
__global__ void __launch_bounds__(256, 2)
pv_gemm()
{
    constexpr int NC = 64;
    constexpr uint32_t STG = 24576, AHI = 0, ALO = 8192, BHI = 16384, BLO = 20480;
    extern __shared__ char smp[];
    const int t = threadIdx.x, lane = t & 31, wid = t >> 5;
    const int wm = (wid >> 2) * 64, wn = (wid & 3) * 16;
    const int bm0 = blockIdx.y * 128, z = blockIdx.z;
    const uint32_t smb = smem_u32(smp);

    const __nv_bfloat16* Ahg = g_Shi + (size_t)z * LLEN * SLEN + (size_t)bm0 * 2048;
    const __nv_bfloat16* Alg = g_Slo + (size_t)z * LLEN * SLEN + (size_t)bm0 * 2048;
    const __nv_bfloat16* Bhg = g_Vhi + (size_t)z * DHEAD * SLEN;
    const __nv_bfloat16* Blg = g_Vlo + (size_t)z * DHEAD * SLEN;

    auto issue = [&](int c) {
        const uint32_t sb = (uint32_t)(c % 3) * STG;
        #pragma unroll
        for (int i = 0; i < 2; i++) {
            const int idx = t + 256 * i;
            const int r = idx >> 2, kc = idx & 3;
            const uint32_t so = r * 64 + ((uint32_t)(kc ^ ((r >> 1) & 3)) << 4);
            const size_t go = (size_t)r * 2048 + c * 32 + kc * 8;
            CPA16(smb + sb + AHI + so, Ahg + go);
            CPA16(smb + sb + ALO + so, Alg + go);
        }
        {
            const int r = t >> 2, kc = t & 3;   // 64 rows x 4 chunks
            const uint32_t so = r * 64 + ((uint32_t)(kc ^ ((r >> 1) & 3)) << 4);
            const size_t go = (size_t)r * 2048 + c * 32 + kc * 8;
            CPA16(smb + sb + BHI + so, Bhg + go);
            CPA16(smb + sb + BLO + so, Blg + go);
        }
        CPCOMMIT();
    };

    issue(0); issue(1); issue(2);

    float acc[4][2][4];
    #pragma unroll
    for (int m = 0; m < 4; m++)
        #pragma unroll
        for (int n = 0; n < 2; n++)
            #pragma unroll
            for (int v = 0; v < 4; v++) acc[m][n][v] = 0.0f;

    const int arow  = wm + ((lane >> 3) & 1) * 8 + (lane & 7);
    const int acsel = lane >> 4;
    const int brow  = wn + (lane >> 4) * 8 + (lane & 7);
    const int bcsel = (lane >> 3) & 1;

    for (int c = 0; c < NC; c++) {
        if (c + 2 < NC) { CPWAIT2(); } else if (c + 1 < NC) { CPWAIT1(); } else { CPWAIT0(); }
        __syncthreads();
        const uint32_t sb = (uint32_t)(c % 3) * STG;
        #pragma unroll
        for (int kk = 0; kk < 2; kk++) {
            uint32_t Bh[2][2], Bl[2][2];
            {
                const int r = brow, kc = kk * 2 + bcsel;
                const uint32_t ba = smb + sb + BHI + r * 64 +
                    ((uint32_t)(kc ^ ((r >> 1) & 3)) << 4);
                ldsm4(Bh[0][0], Bh[0][1], Bh[1][0], Bh[1][1], ba);
                ldsm4(Bl[0][0], Bl[0][1], Bl[1][0], Bl[1][1], ba + (BLO - BHI));
            }
            #pragma unroll
            for (int mt = 0; mt < 4; mt++) {
                const int r = arow + mt * 16, kc = kk * 2 + acsel;
                const uint32_t aa = smb + sb + AHI + r * 64 +
                    ((uint32_t)(kc ^ ((r >> 1) & 3)) << 4);
                uint32_t Ah[4], Al[4];
                ldsm4(Ah[0], Ah[1], Ah[2], Ah[3], aa);
                ldsm4(Al[0], Al[1], Al[2], Al[3], aa + (ALO - AHI));
                #pragma unroll
                for (int nt = 0; nt < 2; nt++) {
                    mma16816(acc[mt][nt], Ah, Bh[nt]);
                    mma16816(acc[mt][nt], Al, Bh[nt]);
                    mma16816(acc[mt][nt], Ah, Bl[nt]);
                }
            }
        }
        __syncthreads();
        if (c + 3 < NC) issue(c + 3);
    }

    const int n = z >> 4, h = z & 15;
    #pragma unroll
    for (int mt = 0; mt < 4; mt++) {
        const int r = bm0 + wm + mt * 16 + (lane >> 2);
        #pragma unroll
        for (int nt = 0; nt < 2; nt++) {
            const int cl = wn + nt * 8 + (lane & 3) * 2;
            const size_t a0 = (size_t)r * (NBAT * EDIM) + n * EDIM + h * DHEAD + cl;
            const size_t a1 = a0 + (size_t)8 * (NBAT * EDIM);
            const float h0 = bfhi(acc[mt][nt][0]), h1 = bfhi(acc[mt][nt][1]);
            const float h2 = bfhi(acc[mt][nt][2]), h3 = bfhi(acc[mt][nt][3]);
            *(uint32_t*)(g_Chi + a0) = bfpack(h0, h1);
            *(uint32_t*)(g_Clo + a0) = bfpack(acc[mt][nt][0] - h0, acc[mt][nt][1] - h1);
            *(uint32_t*)(g_Chi + a1) = bfpack(h2, h3);
            *(uint32_t*)(g_Clo + a1) = bfpack(acc[mt][nt][2] - h2, acc[mt][nt][3] - h3);
        }
    }
}

// ---------------- fast exp on FMA pipe ----------------
__device__ __forceinline__ float fexp(float x)
{
    float y = x * 1.4426950408889634f;
    y = fmaxf(y, -120.0f);
    float r = rintf(y);
    float f = y - r;
    float p = 1.3333558146e-3f;
    p = fmaf(p, f, 9.6181291076e-3f);
    p = fmaf(p, f, 5.5504108665e-2f);
    p = fmaf(p, f, 2.4022650696e-1f);
    p = fmaf(p, f, 6.9314718056e-1f);
    p = fmaf(p, f, 1.0f);
    return p * __int_as_float(((int)r + 127) << 23);
}

// ---------------- fused softmax (16 heads) + head-mean; in-place probs ------
__global__ void __launch_bounds__(256)
softmax_mean_k(float* __restrict__ wavg)
{
    const int b = blockIdx.x;
    const int n = b >> 11, l = b & 2047;
    const int t = threadIdx.x;
    __shared__ float sh[8];
    float mean[8];
    #pragma unroll
    for (int i = 0; i < 8; i++) mean[i] = 0.0f;

    for (int h = 0; h < NHEAD; h++) {
        const size_t base = (((size_t)(n * NHEAD + h) * LLEN) + l) * SLEN + (size_t)t * 8;
        const uint4 ph = *(const uint4*)(g_Shi + base);
        const uint4 pl = *(const uint4*)(g_Slo + base);
        float x[8];
        {
            float2 a, c;
            a = bfunpack2(ph.x); c = bfunpack2(pl.x); x[0] = a.x + c.x; x[1] = a.y + c.y;
            a = bfunpack2(ph.y); c = bfunpack2(pl.y); x[2] = a.x + c.x; x[3] = a.y + c.y;
            a = bfunpack2(ph.z); c = bfunpack2(pl.z); x[4] = a.x + c.x; x[5] = a.y + c.y;
            a = bfunpack2(ph.w); c = bfunpack2(pl.w); x[6] = a.x + c.x; x[7] = a.y + c.y;
        }
        float m = x[0];
        #pragma unroll
        for (int i = 1; i < 8; i++) m = fmaxf(m, x[i]);
        #pragma unroll
        for (int o = 16; o > 0; o >>= 1) m = fmaxf(m, __shfl_xor_sync(0xffffffffu, m, o));
        if ((t & 31) == 0) sh[t >> 5] = m;
        __syncthreads();
        m = sh[t & 7];
        #pragma unroll
        for (int o = 4; o > 0; o >>= 1) m = fmaxf(m, __shfl_xor_sync(0xffffffffu, m, o));
        float s = 0.0f;
        #pragma unroll
        for (int i = 0; i < 8; i++) { x[i] = fexp(x[i] - m); s += x[i]; }
        #pragma unroll
        for (int o = 16; o > 0; o >>= 1) s += __shfl_xor_sync(0xffffffffu, s, o);
        __syncthreads();
        if ((t & 31) == 0) sh[t >> 5] = s;
        __syncthreads();
        s = sh[t & 7];
        #pragma unroll
        for (int o = 4; o > 0; o >>= 1) s += __shfl_xor_sync(0xffffffffu, s, o);
        const float inv = 1.0f / s;
        uint4 oh, ol;
        float hx, hy;
        #pragma unroll
        for (int i = 0; i < 8; i++) { x[i] *= inv; mean[i] += x[i]; }
        hx = bfhi(x[0]); hy = bfhi(x[1]);
        oh.x = bfpack(hx, hy); ol.x = bfpack(x[0] - hx, x[1] - hy);
        hx = bfhi(x[2]); hy = bfhi(x[3]);
        oh.y = bfpack(hx, hy); ol.y = bfpack(x[2] - hx, x[3] - hy);
        hx = bfhi(x[4]); hy = bfhi(x[5]);
        oh.z = bfpack(hx, hy); ol.z = bfpack(x[4] - hx, x[5] - hy);
        hx = bfhi(x[6]); hy = bfhi(x[7]);
        oh.w = bfpack(hx, hy); ol.w = bfpack(x[6] - hx, x[7] - hy);
        *(uint4*)(g_Shi + base) = oh;
        *(uint4*)(g_Slo + base) = ol;
        __syncthreads();
    }
    float4* w = (float4*)(wavg + (size_t)b * SLEN + (size_t)t * 8);
    float4 w0 = { mean[0] * 0.0625f, mean[1] * 0.0625f, mean[2] * 0.0625f, mean[3] * 0.0625f };
    float4 w1 = { mean[4] * 0.0625f, mean[5] * 0.0625f, mean[6] * 0.0625f, mean[7] * 0.0625f };
    w[0] = w0;
    w[1] = w1;
}

// ---------------- launcher ----------------
extern "C" void kernel_launch(void* const* d_in, const int* in_sizes, int n_in,
                              void* d_out, int out_size)
{
    const float* query = (const float*)d_in[0];
    const float* key   = (const float*)d_in[1];
    const float* value = (const float*)d_in[2];
    const float* Wq = (const float*)d_in[3];  const float* bq = (const float*)d_in[4];
    const float* Wk = (const float*)d_in[5];  const float* bk = (const float*)d_in[6];
    const float* Wv = (const float*)d_in[7];  const float* bv = (const float*)d_in[8];
    const float* Wo = (const float*)d_in[9];  const float* bo = (const float*)d_in[10];
    float* out  = (float*)d_out;
    float* wavg = out + (size_t)LLEN * NBAT * EDIM;

    const int SQKV = 98304;   // 3 x 32KB stages; epilogue stage 67584 fits
    const int SO   = 98304;
    const int SQK  = 69632;
    const int SPV  = 73728;   // 3 x 24KB stages
    cudaFuncSetAttribute(qkv_gemm, cudaFuncAttributeMaxDynamicSharedMemorySize, SQKV);
    cudaFuncSetAttribute(out_gemm, cudaFuncAttributeMaxDynamicSharedMemorySize, SO);
    cudaFuncSetAttribute(qk_gemm,  cudaFuncAttributeMaxDynamicSharedMemorySize, SQK);
    cudaFuncSetAttribute(pv_gemm,  cudaFuncAttributeMaxDynamicSharedMemorySize, SPV);

    dim3 thr(256);
    split_k<<<dim3(4096, 1, 7), thr>>>(query, key, value, Wq, Wk, Wv, Wo);
    qkv_gemm<<<dim3(8, 64, 3), thr, SQKV>>>(bq, bk, bv);
    qk_gemm<<<dim3(16, 16, 64), thr, SQK>>>();
    softmax_mean_k<<<NBAT * LLEN, thr>>>(wavg);
    pv_gemm<<<dim3(1, 16, 64), thr, SPV>>>();
    out_gemm<<<dim3(8, 64, 1), thr, SO>>>(bo, out);
}